// round 10
// baseline (speedup 1.0000x reference)
#include <cuda_runtime.h>
#include <cuda_fp16.h>
#include <cstdint>
#include <math.h>

// Problem dims (fixed by reference setup_inputs)
#define BB 4
#define TT 4096
#define HH 1024
#define M_TOTAL (BB*TT)      // 16384
#define NCHUNK 128
#define CHUNK (TT/NCHUNK)    // 32

// Scratch (allocation-free rule: __device__ globals)
__device__ __half g_normh[(size_t)M_TOTAL*HH];   // fp16 LN output (32MB)
__device__ __half g_Wh[(size_t)2*HH*HH];         // fp16 [Wg; Wc] (4MB)
__device__ __half g_zh[(size_t)M_TOTAL*HH];      // fp16 gate (32MB)
__device__ __half g_ch[(size_t)M_TOTAL*HH];      // fp16 candidate (32MB)
__device__ float g_P[(size_t)BB*NCHUNK*HH];
__device__ float g_S[(size_t)BB*NCHUNK*HH];
__device__ float g_hin[(size_t)BB*NCHUNK*HH];

__device__ __forceinline__ uint32_t smem_u32(const void* p) {
    uint32_t a;
    asm("{ .reg .u64 t; cvta.to.shared.u64 t, %1; cvt.u32.u64 %0, t; }" : "=r"(a) : "l"(p));
    return a;
}
__device__ __forceinline__ void cp16(uint32_t dst, const void* src) {
    asm volatile("cp.async.cg.shared.global [%0], [%1], 16;" :: "r"(dst), "l"(src));
}

// ---------------------------------------------------------------------------
// Kernel 0: convert Wg/Wc to fp16 into g_Wh
// ---------------------------------------------------------------------------
__global__ void halfW_kernel(const float* __restrict__ Wg,
                             const float* __restrict__ Wc) {
    int i = blockIdx.x * blockDim.x + threadIdx.x;   // over 2*HH*HH/4
    int half_n = HH * HH / 4;
    const float4* src = (i < half_n) ? (const float4*)Wg : (const float4*)Wc;
    float4 v = src[(i < half_n) ? i : (i - half_n)];
    __half2 h0 = __floats2half2_rn(v.x, v.y);
    __half2 h1 = __floats2half2_rn(v.z, v.w);
    ((uint2*)g_Wh)[i] = make_uint2(*(uint32_t*)&h0, *(uint32_t*)&h1);
}

// ---------------------------------------------------------------------------
// Kernel 1: LayerNorm -> fp16 normed. Warp-per-row (8 rows/block).
// ---------------------------------------------------------------------------
__global__ __launch_bounds__(256) void ln_kernel(
    const float* __restrict__ x,
    const float* __restrict__ gamma,
    const float* __restrict__ beta) {
    int warp = threadIdx.x >> 5, lane = threadIdx.x & 31;
    int row = blockIdx.x * 8 + warp;
    const float4* xr = (const float4*)(x + (size_t)row * HH);

    float4 v[8];
    float s = 0.f, s2 = 0.f;
    #pragma unroll
    for (int q = 0; q < 8; q++) {
        v[q] = xr[lane + 32 * q];
        s  += v[q].x + v[q].y + v[q].z + v[q].w;
        s2 += v[q].x*v[q].x + v[q].y*v[q].y + v[q].z*v[q].z + v[q].w*v[q].w;
    }
    #pragma unroll
    for (int o = 16; o > 0; o >>= 1) {
        s  += __shfl_xor_sync(0xFFFFFFFFu, s,  o);
        s2 += __shfl_xor_sync(0xFFFFFFFFu, s2, o);
    }
    float mu  = s * (1.f / HH);
    float var = s2 * (1.f / HH) - mu * mu;
    float rs  = rsqrtf(var + 1e-5f);

    uint2* orow = (uint2*)g_normh + (size_t)row * (HH / 4);
    #pragma unroll
    for (int q = 0; q < 8; q++) {
        int f = lane + 32 * q;
        float4 g  = ((const float4*)gamma)[f];
        float4 bt = ((const float4*)beta)[f];
        __half2 h0 = __floats2half2_rn((v[q].x - mu) * rs * g.x + bt.x,
                                       (v[q].y - mu) * rs * g.y + bt.y);
        __half2 h1 = __floats2half2_rn((v[q].z - mu) * rs * g.z + bt.z,
                                       (v[q].w - mu) * rs * g.w + bt.w);
        orow[f] = make_uint2(*(uint32_t*)&h0, *(uint32_t*)&h1);
    }
}

// ---------------------------------------------------------------------------
// Kernel 2: fused dual GEMM (gate + candidate) + in-CTA chunk aggregates.
// fp16 mma.sync m16n8k16, cp.async 3-stage, ldmatrix. Block tile 128(M)x128(N)
// computed against BOTH Wg and Wc (A fragments reused 2x). 256 thr, 8 warps,
// warp tile 64x32 per matrix. Epilogue: sigmoid(z), write z/c to gmem AND
// smem, then per-(chunk,hid) scan over 32 t-steps -> g_P/g_S (scanA fused).
// ---------------------------------------------------------------------------
#define BM 128
#define BN 128
#define BK 32                            // halves per K-tile
#define STAGES 3
#define SSTR_H 40                        // halves per smem row (80B)
#define T_STAGE_H (BM*SSTR_H)            // 5120 halves per tile (A, Bz, Bc each)
#define STAGE_BYTES (3*T_STAGE_H*2)      // 30720 B
#define GEMM_SMEM (STAGES*STAGE_BYTES)   // 92160 B
// epilogue overlay: z,c tiles as half2[128][68] each (272B row stride)
#define EP_STRIDE 68
#define EP_TILE_BYTES (128*EP_STRIDE*4)  // 34816 B

__global__ __launch_bounds__(256, 1) void gemm_kernel(
    const float* __restrict__ bg, const float* __restrict__ bc)
{
    extern __shared__ char smc[];
    uint32_t s_base = smem_u32(smc);

    int tid = threadIdx.x;               // 256
    int warp = tid >> 5, lane = tid & 31;
    int bn = blockIdx.x;                 // 0..7
    int bm = blockIdx.y;                 // 0..127
    int wm = (warp & 1) * 64;            // 2 M-warps
    int wn = (warp >> 1) * 32;           // 4 N-warps

    int nbase = bn * BN;
    size_t arow = (size_t)bm * BM;

    const __half* Asrc0 = g_normh + arow * HH;
    const __half* Bzsrc0 = g_Wh + (size_t)nbase * HH;
    const __half* Bcsrc0 = g_Wh + (size_t)HH * HH + (size_t)nbase * HH;

    float accz[4][4][4], accc[4][4][4];  // 4 m16 x 4 n8 x 4 regs, per matrix
    #pragma unroll
    for (int i = 0; i < 4; i++)
        #pragma unroll
        for (int j = 0; j < 4; j++)
            #pragma unroll
            for (int q = 0; q < 4; q++) { accz[i][j][q] = 0.f; accc[i][j][q] = 0.f; }

    // per stage: A/Bz/Bc each 512 16B-chunks, 256 thr -> 2 each
    int lr[2], lc[2];
    #pragma unroll
    for (int q = 0; q < 2; q++) {
        int f = tid + q * 256;
        lr[q] = f >> 2;                  // row 0..127
        lc[q] = (f & 3) * 8;             // half offset in row
    }

    #define LOAD_STAGE(s, k0) do { \
        uint32_t st = s_base + (uint32_t)(s) * STAGE_BYTES; \
        _Pragma("unroll") \
        for (int q = 0; q < 2; q++) { \
            uint32_t so = (uint32_t)(lr[q] * SSTR_H + lc[q]) * 2; \
            size_t go = (size_t)lr[q] * HH + (k0) + lc[q]; \
            cp16(st + so,                      Asrc0  + go); \
            cp16(st + T_STAGE_H*2 + so,        Bzsrc0 + go); \
            cp16(st + T_STAGE_H*4 + so,        Bcsrc0 + go); \
        } \
    } while (0)

    LOAD_STAGE(0, 0);
    asm volatile("cp.async.commit_group;");
    LOAD_STAGE(1, BK);
    asm volatile("cp.async.commit_group;");

    uint32_t a_row = (uint32_t)(lane & 15);
    uint32_t a_kb  = ((lane >> 4) & 1) * 16;
    uint32_t b_row = (uint32_t)((lane & 7) + ((lane >> 4) & 1) * 8);
    uint32_t b_kb  = ((lane >> 3) & 1) * 16;

    const int NK = HH / BK;              // 32
    for (int i = 0; i < NK; i++) {
        int s = i % STAGES;
        asm volatile("cp.async.wait_group 1;");
        __syncthreads();
        if (i + 2 < NK) {
            int s2 = (i + 2) % STAGES;
            LOAD_STAGE(s2, (i + 2) * BK);
        }
        asm volatile("cp.async.commit_group;");

        uint32_t abase = s_base + (uint32_t)s * STAGE_BYTES;
        uint32_t zbase = abase + T_STAGE_H * 2;
        uint32_t cbase = abase + T_STAGE_H * 4;

        #pragma unroll
        for (int ks = 0; ks < 2; ks++) {
            unsigned af[4][4];
            #pragma unroll
            for (int ii = 0; ii < 4; ii++) {
                uint32_t addr = abase + (wm + ii * 16 + a_row) * (SSTR_H * 2)
                                + ks * 32 + a_kb;
                asm volatile(
                    "ldmatrix.sync.aligned.m8n8.x4.shared.b16 {%0,%1,%2,%3}, [%4];"
                    : "=r"(af[ii][0]), "=r"(af[ii][1]), "=r"(af[ii][2]), "=r"(af[ii][3])
                    : "r"(addr));
            }
            unsigned bfz[4][2], bfc[4][2];
            #pragma unroll
            for (int j2 = 0; j2 < 2; j2++) {
                uint32_t za = zbase + (wn + j2 * 16 + b_row) * (SSTR_H * 2)
                              + ks * 32 + b_kb;
                asm volatile(
                    "ldmatrix.sync.aligned.m8n8.x4.shared.b16 {%0,%1,%2,%3}, [%4];"
                    : "=r"(bfz[j2*2][0]), "=r"(bfz[j2*2][1]),
                      "=r"(bfz[j2*2+1][0]), "=r"(bfz[j2*2+1][1])
                    : "r"(za));
                uint32_t ca = cbase + (wn + j2 * 16 + b_row) * (SSTR_H * 2)
                              + ks * 32 + b_kb;
                asm volatile(
                    "ldmatrix.sync.aligned.m8n8.x4.shared.b16 {%0,%1,%2,%3}, [%4];"
                    : "=r"(bfc[j2*2][0]), "=r"(bfc[j2*2][1]),
                      "=r"(bfc[j2*2+1][0]), "=r"(bfc[j2*2+1][1])
                    : "r"(ca));
            }
            #pragma unroll
            for (int ii = 0; ii < 4; ii++) {
                #pragma unroll
                for (int j = 0; j < 4; j++) {
                    float* az = accz[ii][j];
                    asm volatile(
                        "mma.sync.aligned.m16n8k16.row.col.f32.f16.f16.f32 "
                        "{%0,%1,%2,%3},{%4,%5,%6,%7},{%8,%9},{%0,%1,%2,%3};"
                        : "+f"(az[0]), "+f"(az[1]), "+f"(az[2]), "+f"(az[3])
                        : "r"(af[ii][0]), "r"(af[ii][1]), "r"(af[ii][2]), "r"(af[ii][3]),
                          "r"(bfz[j][0]), "r"(bfz[j][1]));
                    float* ac = accc[ii][j];
                    asm volatile(
                        "mma.sync.aligned.m16n8k16.row.col.f32.f16.f16.f32 "
                        "{%0,%1,%2,%3},{%4,%5,%6,%7},{%8,%9},{%0,%1,%2,%3};"
                        : "+f"(ac[0]), "+f"(ac[1]), "+f"(ac[2]), "+f"(ac[3])
                        : "r"(af[ii][0]), "r"(af[ii][1]), "r"(af[ii][2]), "r"(af[ii][3]),
                          "r"(bfc[j][0]), "r"(bfc[j][1]));
                }
            }
        }
    }
    asm volatile("cp.async.wait_group 0;");
    __syncthreads();    // all warps done with pipeline smem before overlay

    // --- Epilogue 1: sigmoid/bias, write z,c to gmem and smem overlay ---
    uint32_t* sz = (uint32_t*)smc;                         // half2[128][68]
    uint32_t* sc = (uint32_t*)(smc + EP_TILE_BYTES);
    int r  = lane >> 2;
    int cq = (lane & 3) * 2;
    #pragma unroll
    for (int ii = 0; ii < 4; ii++) {
        #pragma unroll
        for (int j = 0; j < 4; j++) {
            int tl = wm + ii * 16 + r;               // local row (t within tile)
            int n0 = nbase + wn + j * 8 + cq;
            int hp = (wn + j * 8) / 2 + (lane & 3);  // local half2 col 0..63
            float b0 = bg[n0], b1 = bg[n0 + 1];
            float c0 = bc[n0], c1 = bc[n0 + 1];
            float* az = accz[ii][j];
            float* ac = accc[ii][j];
            float z0 = 1.f / (1.f + __expf(-(az[0] + b0)));
            float z1 = 1.f / (1.f + __expf(-(az[1] + b1)));
            float z2 = 1.f / (1.f + __expf(-(az[2] + b0)));
            float z3 = 1.f / (1.f + __expf(-(az[3] + b1)));
            __half2 hz0 = __floats2half2_rn(z0, z1);
            __half2 hz1 = __floats2half2_rn(z2, z3);
            __half2 hc0 = __floats2half2_rn(ac[0] + c0, ac[1] + c1);
            __half2 hc1 = __floats2half2_rn(ac[2] + c0, ac[3] + c1);
            size_t m0 = arow + tl;
            *(__half2*)(g_zh + m0 * HH + n0)        = hz0;
            *(__half2*)(g_zh + (m0 + 8) * HH + n0)  = hz1;
            *(__half2*)(g_ch + m0 * HH + n0)        = hc0;
            *(__half2*)(g_ch + (m0 + 8) * HH + n0)  = hc1;
            sz[tl * EP_STRIDE + hp]       = *(uint32_t*)&hz0;
            sz[(tl + 8) * EP_STRIDE + hp] = *(uint32_t*)&hz1;
            sc[tl * EP_STRIDE + hp]       = *(uint32_t*)&hc0;
            sc[(tl + 8) * EP_STRIDE + hp] = *(uint32_t*)&hc1;
        }
    }
    __syncthreads();

    // --- Epilogue 2: per-(chunk, hid-pair) scan over 32 t-steps -> P,S ---
    {
        int chunk = tid >> 6;            // 0..3
        int hp    = tid & 63;            // half2 col
        float2 P = make_float2(1.f, 1.f), S = make_float2(0.f, 0.f);
        #pragma unroll
        for (int t = 0; t < CHUNK; t++) {
            int tt = chunk * CHUNK + t;
            __half2 zh = *(__half2*)&sz[tt * EP_STRIDE + hp];
            __half2 ch = *(__half2*)&sc[tt * EP_STRIDE + hp];
            float2 z = __half22float2(zh);
            float2 c = __half22float2(ch);
            float ax = 1.f - z.x, ay = 1.f - z.y;
            S.x = ax * S.x + z.x * c.x;  P.x *= ax;
            S.y = ay * S.y + z.y * c.y;  P.y *= ay;
        }
        int b  = bm >> 5;                          // TT/BM = 32 tiles per batch
        int ck = (bm & 31) * 4 + chunk;
        size_t o = ((size_t)(b * NCHUNK + ck)) * (HH / 2) + (nbase >> 1) + hp;
        ((float2*)g_P)[o] = P;
        ((float2*)g_S)[o] = S;
    }
}

// ---------------------------------------------------------------------------
// Scan phase B: Kogge-Stone over 128 chunk aggregates per (b,hid).
// One warp per (b,hid); each lane composes 4 chunks, 5-step shfl scan,
// then emits 4 h_in values.
// ---------------------------------------------------------------------------
__global__ void scanB_kernel() {
    int gt   = blockIdx.x * blockDim.x + threadIdx.x;
    int lane = gt & 31;
    int wg   = gt >> 5;                 // 0..BB*HH-1
    int hid  = wg & (HH - 1);
    int b    = wg >> 10;                // HH = 1024
    int k0   = 4 * lane;
    size_t i0 = ((size_t)(b * NCHUNK + k0)) * HH + hid;
    float Pk[4], Sk[4];
    #pragma unroll
    for (int q = 0; q < 4; q++) {
        Pk[q] = g_P[i0 + (size_t)q * HH];
        Sk[q] = g_S[i0 + (size_t)q * HH];
    }
    float cP = Pk[0], cS = Sk[0];
    #pragma unroll
    for (int q = 1; q < 4; q++) { cS = Pk[q] * cS + Sk[q]; cP = Pk[q] * cP; }
    #pragma unroll
    for (int d = 1; d < 32; d <<= 1) {
        float pP = __shfl_up_sync(0xFFFFFFFFu, cP, d);
        float pS = __shfl_up_sync(0xFFFFFFFFu, cS, d);
        if (lane >= d) { cS = cP * pS + cS; cP = cP * pP; }
    }
    float h = __shfl_up_sync(0xFFFFFFFFu, cS, 1);
    if (lane == 0) h = 0.f;
    #pragma unroll
    for (int q = 0; q < 4; q++) {
        size_t idx = i0 + (size_t)q * HH;
        g_hin[idx] = h;
        h = Pk[q] * h + Sk[q];
    }
}

// ---------------------------------------------------------------------------
// Scan phase C: re-run each chunk with the correct h_in, fuse residual +x.
// 2 hids/thread via half2/float2.
// ---------------------------------------------------------------------------
__global__ void scanC_kernel(const float* __restrict__ x, float* __restrict__ out) {
    int g2  = blockIdx.x * blockDim.x + threadIdx.x;   // over BB*NCHUNK*HH/2
    int hp  = g2 % (HH / 2);
    int ck  = (g2 / (HH / 2)) % NCHUNK;
    int b   = g2 / ((HH / 2) * NCHUNK);
    size_t base = ((size_t)(b * TT + ck * CHUNK)) * HH + 2 * hp;
    float2 h = ((const float2*)g_hin)[((size_t)(b * NCHUNK + ck)) * (HH / 2) + hp];
    #pragma unroll
    for (int t = 0; t < CHUNK; t++) {
        size_t idx = base + (size_t)t * HH;
        float2 z = __half22float2(*(const __half2*)(g_zh + idx));
        float2 c = __half22float2(*(const __half2*)(g_ch + idx));
        h.x = (1.f - z.x) * h.x + z.x * c.x;
        h.y = (1.f - z.y) * h.y + z.y * c.y;
        float2 xv = *(const float2*)(x + idx);
        *(float2*)(out + idx) = make_float2(h.x + xv.x, h.y + xv.y);
    }
}

// ---------------------------------------------------------------------------
extern "C" void kernel_launch(void* const* d_in, const int* in_sizes, int n_in,
                              void* d_out, int out_size) {
    const float* x     = (const float*)d_in[0];
    const float* gamma = (const float*)d_in[1];
    const float* beta  = (const float*)d_in[2];
    const float* Wg    = (const float*)d_in[3];
    const float* bg    = (const float*)d_in[4];
    const float* Wc    = (const float*)d_in[5];
    const float* bc    = (const float*)d_in[6];
    float* out = (float*)d_out;

    halfW_kernel<<<(2 * HH * HH / 4) / 256, 256>>>(Wg, Wc);
    ln_kernel<<<M_TOTAL / 8, 256>>>(x, gamma, beta);

    cudaFuncSetAttribute(gemm_kernel,
                         cudaFuncAttributeMaxDynamicSharedMemorySize, GEMM_SMEM);
    dim3 ggrid(HH / BN, M_TOTAL / BM);   // (8, 128)
    gemm_kernel<<<ggrid, 256, GEMM_SMEM>>>(bg, bc);

    scanB_kernel<<<(BB * HH * 32) / 256, 256>>>();
    scanC_kernel<<<(BB * NCHUNK * HH / 2) / 256, 256>>>(x, out);
}

// round 11
// speedup vs baseline: 1.0478x; 1.0478x over previous
#include <cuda_runtime.h>
#include <cuda_fp16.h>
#include <cstdint>
#include <math.h>

// Problem dims (fixed by reference setup_inputs)
#define BB 4
#define TT 4096
#define HH 1024
#define M_TOTAL (BB*TT)      // 16384
#define NCHUNK 64
#define CHUNK (TT/NCHUNK)    // 64

// Scratch (allocation-free rule: __device__ globals)
__device__ __half g_normh[(size_t)M_TOTAL*HH];   // fp16 LN output (32MB)
__device__ __half g_Wh[(size_t)2*HH*HH];         // fp16 [Wg; Wc] (4MB)
__device__ __half2 g_zc[(size_t)M_TOTAL*HH];     // interleaved (z,c) per hid (64MB)
__device__ float g_P[BB*NCHUNK*HH];
__device__ float g_S[BB*NCHUNK*HH];
__device__ float g_hin[BB*NCHUNK*HH];

__device__ __forceinline__ uint32_t smem_u32(const void* p) {
    uint32_t a;
    asm("{ .reg .u64 t; cvta.to.shared.u64 t, %1; cvt.u32.u64 %0, t; }" : "=r"(a) : "l"(p));
    return a;
}
__device__ __forceinline__ void cp16(uint32_t dst, const void* src) {
    asm volatile("cp.async.cg.shared.global [%0], [%1], 16;" :: "r"(dst), "l"(src));
}

// ---------------------------------------------------------------------------
// Kernel 0: convert Wg/Wc to fp16 into g_Wh
// ---------------------------------------------------------------------------
__global__ void halfW_kernel(const float* __restrict__ Wg,
                             const float* __restrict__ Wc) {
    int i = blockIdx.x * blockDim.x + threadIdx.x;   // over 2*HH*HH/4
    int half_n = HH * HH / 4;
    const float4* src = (i < half_n) ? (const float4*)Wg : (const float4*)Wc;
    float4 v = src[(i < half_n) ? i : (i - half_n)];
    __half2 h0 = __floats2half2_rn(v.x, v.y);
    __half2 h1 = __floats2half2_rn(v.z, v.w);
    ((uint2*)g_Wh)[i] = make_uint2(*(uint32_t*)&h0, *(uint32_t*)&h1);
}

// ---------------------------------------------------------------------------
// Kernel 1: LayerNorm -> fp16 normed. Warp-per-row (8 rows/block), pure
// shfl reduction, 8 float4/lane in flight, no block barrier.
// ---------------------------------------------------------------------------
__global__ __launch_bounds__(256) void ln_kernel(
    const float* __restrict__ x,
    const float* __restrict__ gamma,
    const float* __restrict__ beta) {
    int warp = threadIdx.x >> 5, lane = threadIdx.x & 31;
    int row = blockIdx.x * 8 + warp;
    const float4* xr = (const float4*)(x + (size_t)row * HH);

    float4 v[8];
    float s = 0.f, s2 = 0.f;
    #pragma unroll
    for (int q = 0; q < 8; q++) {
        v[q] = xr[lane + 32 * q];
        s  += v[q].x + v[q].y + v[q].z + v[q].w;
        s2 += v[q].x*v[q].x + v[q].y*v[q].y + v[q].z*v[q].z + v[q].w*v[q].w;
    }
    #pragma unroll
    for (int o = 16; o > 0; o >>= 1) {
        s  += __shfl_xor_sync(0xFFFFFFFFu, s,  o);
        s2 += __shfl_xor_sync(0xFFFFFFFFu, s2, o);
    }
    float mu  = s * (1.f / HH);
    float var = s2 * (1.f / HH) - mu * mu;
    float rs  = rsqrtf(var + 1e-5f);

    uint2* orow = (uint2*)g_normh + (size_t)row * (HH / 4);
    #pragma unroll
    for (int q = 0; q < 8; q++) {
        int f = lane + 32 * q;
        float4 g  = ((const float4*)gamma)[f];
        float4 bt = ((const float4*)beta)[f];
        __half2 h0 = __floats2half2_rn((v[q].x - mu) * rs * g.x + bt.x,
                                       (v[q].y - mu) * rs * g.y + bt.y);
        __half2 h1 = __floats2half2_rn((v[q].z - mu) * rs * g.z + bt.z,
                                       (v[q].w - mu) * rs * g.w + bt.w);
        orow[f] = make_uint2(*(uint32_t*)&h0, *(uint32_t*)&h1);
    }
}

// ---------------------------------------------------------------------------
// Kernel 2: fp16 mma.sync (m16n8k16) GEMM, cp.async 4-stage pipeline,
// ldmatrix fragment loads. Block tile 128x128, BK=32, 4 warps (128 thr),
// warp tile 64x64 (2x2 warp grid). 2 CTAs/SM. At the mma.sync HMMA ceiling.
// Logical N = 2048: bn<8 -> Wg+sigmoid (z), bn>=8 -> Wc (c); both write the
// interleaved g_zc buffer: g_zc[m][hid] = (z, c) as __half2.
// ---------------------------------------------------------------------------
#define BM 128
#define BN 128
#define BK 32                            // halves per K-tile
#define STAGES 4
#define SSTR_H 40                        // halves per smem row (80B: ldmatrix conflict-free)
#define A_STAGE_H (BM*SSTR_H)            // 5120 halves
#define B_STAGE_H (BN*SSTR_H)
#define GEMM_SMEM (STAGES*(A_STAGE_H+B_STAGE_H)*2)   // 81920 B

__global__ __launch_bounds__(128, 2) void gemm_kernel(
    const float* __restrict__ bg, const float* __restrict__ bc)
{
    extern __shared__ __half smh[];
    uint32_t sA_u = smem_u32(smh);
    uint32_t sB_u = sA_u + STAGES * A_STAGE_H * 2;

    int tid = threadIdx.x;               // 128
    int warp = tid >> 5, lane = tid & 31;
    int bn = blockIdx.x;                 // 0..15 (fast -> wave shares A in L2)
    int bm = blockIdx.y;                 // 0..127
    int wm = (warp & 1) * 64;            // 2 M-warps
    int wn = (warp >> 1) * 64;           // 2 N-warps

    bool isGate = (bn < 8);
    size_t woff = isGate ? 0 : (size_t)HH * HH;
    int nbase = (bn & 7) * BN;
    size_t arow = (size_t)bm * BM;

    const __half* Asrc0 = g_normh + arow * HH;
    const __half* Bsrc0 = g_Wh + woff + (size_t)nbase * HH;

    float acc[4][8][4];                  // 4 m16 x 8 n8 x 4 regs
    #pragma unroll
    for (int i = 0; i < 4; i++)
        #pragma unroll
        for (int j = 0; j < 8; j++)
            #pragma unroll
            for (int q = 0; q < 4; q++) acc[i][j][q] = 0.f;

    // loads: per stage A 512 + B 512 16B-chunks, 128 thr -> 4+4 each
    int lr[4], lc[4];
    #pragma unroll
    for (int q = 0; q < 4; q++) {
        int f = tid + q * 128;
        lr[q] = f >> 2;                  // row 0..127
        lc[q] = (f & 3) * 8;             // half offset in row (16B chunks)
    }

    #define LOAD_STAGE(s, k0) do { \
        uint32_t abase = sA_u + (uint32_t)(s) * A_STAGE_H * 2; \
        uint32_t bbase = sB_u + (uint32_t)(s) * B_STAGE_H * 2; \
        _Pragma("unroll") \
        for (int q = 0; q < 4; q++) { \
            cp16(abase + (uint32_t)(lr[q] * SSTR_H + lc[q]) * 2, \
                 Asrc0 + (size_t)lr[q] * HH + (k0) + lc[q]); \
            cp16(bbase + (uint32_t)(lr[q] * SSTR_H + lc[q]) * 2, \
                 Bsrc0 + (size_t)lr[q] * HH + (k0) + lc[q]); \
        } \
    } while (0)

    LOAD_STAGE(0, 0);
    asm volatile("cp.async.commit_group;");
    LOAD_STAGE(1, BK);
    asm volatile("cp.async.commit_group;");
    LOAD_STAGE(2, 2 * BK);
    asm volatile("cp.async.commit_group;");

    // per-lane ldmatrix address components (bytes)
    uint32_t a_row = (uint32_t)(lane & 15);          // row within m16
    uint32_t a_kb  = ((lane >> 4) & 1) * 16;         // +8 halves
    uint32_t b_row = (uint32_t)((lane & 7) + ((lane >> 4) & 1) * 8);  // row within n16
    uint32_t b_kb  = ((lane >> 3) & 1) * 16;

    const int NK = HH / BK;              // 32
    for (int i = 0; i < NK; i++) {
        int s = i & (STAGES - 1);
        asm volatile("cp.async.wait_group 2;");
        __syncthreads();
        if (i + 3 < NK) {
            int s2 = (i + 3) & (STAGES - 1);
            LOAD_STAGE(s2, (i + 3) * BK);
        }
        asm volatile("cp.async.commit_group;");

        uint32_t abase = sA_u + (uint32_t)s * A_STAGE_H * 2;
        uint32_t bbase = sB_u + (uint32_t)s * B_STAGE_H * 2;

        #pragma unroll
        for (int ks = 0; ks < 2; ks++) {     // two k16 steps per K-tile
            unsigned af[4][4];
            #pragma unroll
            for (int ii = 0; ii < 4; ii++) {
                uint32_t addr = abase + (wm + ii * 16 + a_row) * (SSTR_H * 2)
                                + ks * 32 + a_kb;
                asm volatile(
                    "ldmatrix.sync.aligned.m8n8.x4.shared.b16 {%0,%1,%2,%3}, [%4];"
                    : "=r"(af[ii][0]), "=r"(af[ii][1]), "=r"(af[ii][2]), "=r"(af[ii][3])
                    : "r"(addr));
            }
            unsigned bf[8][2];
            #pragma unroll
            for (int j2 = 0; j2 < 4; j2++) {  // each x4 covers two n8 subtiles
                uint32_t addr = bbase + (wn + j2 * 16 + b_row) * (SSTR_H * 2)
                                + ks * 32 + b_kb;
                asm volatile(
                    "ldmatrix.sync.aligned.m8n8.x4.shared.b16 {%0,%1,%2,%3}, [%4];"
                    : "=r"(bf[j2*2][0]), "=r"(bf[j2*2][1]),
                      "=r"(bf[j2*2+1][0]), "=r"(bf[j2*2+1][1])
                    : "r"(addr));
            }
            #pragma unroll
            for (int ii = 0; ii < 4; ii++) {
                #pragma unroll
                for (int j = 0; j < 8; j++) {
                    float* a4 = acc[ii][j];
                    asm volatile(
                        "mma.sync.aligned.m16n8k16.row.col.f32.f16.f16.f32 "
                        "{%0,%1,%2,%3},{%4,%5,%6,%7},{%8,%9},{%0,%1,%2,%3};"
                        : "+f"(a4[0]), "+f"(a4[1]), "+f"(a4[2]), "+f"(a4[3])
                        : "r"(af[ii][0]), "r"(af[ii][1]), "r"(af[ii][2]), "r"(af[ii][3]),
                          "r"(bf[j][0]), "r"(bf[j][1]));
                }
            }
        }
    }
    asm volatile("cp.async.wait_group 0;");

    // Epilogue: +bias, optional sigmoid; write interleaved (z,c) halves.
    // Gate CTAs write the .x half of each g_zc element, candidate CTAs the .y
    // half: g_zc[m][n] = (z, c). Each thread owns hids n0 and n0+1 -> two
    // adjacent __half2 elements; z goes to lane .x, c to lane .y.
    int r  = lane >> 2;
    int cq = (lane & 3) * 2;
    const float* bias = isGate ? bg : bc;
    #pragma unroll
    for (int ii = 0; ii < 4; ii++) {
        #pragma unroll
        for (int j = 0; j < 8; j++) {
            float* a4 = acc[ii][j];
            int m0 = bm * BM + wm + ii * 16 + r;
            int n0 = nbase + wn + j * 8 + cq;
            float b0 = bias[n0], b1 = bias[n0 + 1];
            float v0 = a4[0] + b0;
            float v1 = a4[1] + b1;
            float v2 = a4[2] + b0;
            float v3 = a4[3] + b1;
            if (isGate) {
                v0 = 1.f / (1.f + __expf(-v0));
                v1 = 1.f / (1.f + __expf(-v1));
                v2 = 1.f / (1.f + __expf(-v2));
                v3 = 1.f / (1.f + __expf(-v3));
            }
            __half h0 = __float2half_rn(v0);
            __half h1 = __float2half_rn(v1);
            __half h2 = __float2half_rn(v2);
            __half h3 = __float2half_rn(v3);
            __half* zc0 = (__half*)(g_zc + (size_t)m0 * HH + n0);
            __half* zc1 = (__half*)(g_zc + (size_t)(m0 + 8) * HH + n0);
            int off = isGate ? 0 : 1;        // z -> .x, c -> .y
            zc0[off]     = h0;
            zc0[2 + off] = h1;
            zc1[off]     = h2;
            zc1[2 + off] = h3;
        }
    }
}

// ---------------------------------------------------------------------------
// Scan phase A: per-(b, chunk, hid) aggregates. 2 hids/thread; each t-step
// is ONE 8B uint2 load of interleaved (z,c) pairs.
// ---------------------------------------------------------------------------
__global__ void scanA_kernel() {
    int g2  = blockIdx.x * blockDim.x + threadIdx.x;   // over BB*NCHUNK*HH/2
    int hp  = g2 % (HH / 2);
    int ck  = (g2 / (HH / 2)) % NCHUNK;
    int b   = g2 / ((HH / 2) * NCHUNK);
    size_t base = ((size_t)(b * TT + ck * CHUNK)) * HH + 2 * hp;
    float2 P = make_float2(1.f, 1.f), S = make_float2(0.f, 0.f);
    #pragma unroll 8
    for (int t = 0; t < CHUNK; t++) {
        size_t idx = base + (size_t)t * HH;
        const __half2* zc = g_zc + idx;
        float2 p0 = __half22float2(zc[0]);   // (z0, c0)
        float2 p1 = __half22float2(zc[1]);   // (z1, c1)
        float ax = 1.f - p0.x, ay = 1.f - p1.x;
        S.x = ax * S.x + p0.x * p0.y;  P.x *= ax;
        S.y = ay * S.y + p1.x * p1.y;  P.y *= ay;
    }
    size_t o = ((size_t)(b * NCHUNK + ck)) * (HH / 2) + hp;
    ((float2*)g_P)[o] = P;
    ((float2*)g_S)[o] = S;
}

// ---------------------------------------------------------------------------
// Scan phase B: parallel Kogge-Stone over 64 chunk aggregates per (b,hid).
// ---------------------------------------------------------------------------
__global__ void scanB_kernel() {
    int gt   = blockIdx.x * blockDim.x + threadIdx.x;
    int lane = gt & 31;
    int wg   = gt >> 5;                 // 0..BB*HH-1
    int hid  = wg & (HH - 1);
    int b    = wg >> 10;                // HH = 1024
    int k0   = 2 * lane;
    size_t i0 = ((size_t)(b * NCHUNK + k0)) * HH + hid;
    float P0 = g_P[i0],      S0 = g_S[i0];
    float P1 = g_P[i0 + HH], S1 = g_S[i0 + HH];
    float cP = P1 * P0;
    float cS = P1 * S0 + S1;
    #pragma unroll
    for (int d = 1; d < 32; d <<= 1) {
        float pP = __shfl_up_sync(0xFFFFFFFFu, cP, d);
        float pS = __shfl_up_sync(0xFFFFFFFFu, cS, d);
        if (lane >= d) { cS = cP * pS + cS; cP = cP * pP; }
    }
    float eS = __shfl_up_sync(0xFFFFFFFFu, cS, 1);
    if (lane == 0) eS = 0.f;
    g_hin[i0]      = eS;
    g_hin[i0 + HH] = P0 * eS + S0;
}

// ---------------------------------------------------------------------------
// Scan phase C: re-run each chunk with the correct h_in, fuse residual +x.
// 2 hids/thread; one 8B uint2 load of (z,c) pairs per t-step.
// ---------------------------------------------------------------------------
__global__ void scanC_kernel(const float* __restrict__ x, float* __restrict__ out) {
    int g2  = blockIdx.x * blockDim.x + threadIdx.x;   // over BB*NCHUNK*HH/2
    int hp  = g2 % (HH / 2);
    int ck  = (g2 / (HH / 2)) % NCHUNK;
    int b   = g2 / ((HH / 2) * NCHUNK);
    size_t base = ((size_t)(b * TT + ck * CHUNK)) * HH + 2 * hp;
    float2 h = ((const float2*)g_hin)[((size_t)(b * NCHUNK + ck)) * (HH / 2) + hp];
    #pragma unroll 8
    for (int t = 0; t < CHUNK; t++) {
        size_t idx = base + (size_t)t * HH;
        const __half2* zc = g_zc + idx;
        float2 p0 = __half22float2(zc[0]);   // (z0, c0)
        float2 p1 = __half22float2(zc[1]);   // (z1, c1)
        h.x = (1.f - p0.x) * h.x + p0.x * p0.y;
        h.y = (1.f - p1.x) * h.y + p1.x * p1.y;
        float2 xv = *(const float2*)(x + idx);
        *(float2*)(out + idx) = make_float2(h.x + xv.x, h.y + xv.y);
    }
}

// ---------------------------------------------------------------------------
extern "C" void kernel_launch(void* const* d_in, const int* in_sizes, int n_in,
                              void* d_out, int out_size) {
    const float* x     = (const float*)d_in[0];
    const float* gamma = (const float*)d_in[1];
    const float* beta  = (const float*)d_in[2];
    const float* Wg    = (const float*)d_in[3];
    const float* bg    = (const float*)d_in[4];
    const float* Wc    = (const float*)d_in[5];
    const float* bc    = (const float*)d_in[6];
    float* out = (float*)d_out;

    halfW_kernel<<<(2 * HH * HH / 4) / 256, 256>>>(Wg, Wc);
    ln_kernel<<<M_TOTAL / 8, 256>>>(x, gamma, beta);

    cudaFuncSetAttribute(gemm_kernel,
                         cudaFuncAttributeMaxDynamicSharedMemorySize, GEMM_SMEM);
    dim3 ggrid(2 * HH / BN, M_TOTAL / BM);   // (16, 128)
    gemm_kernel<<<ggrid, 128, GEMM_SMEM>>>(bg, bc);

    scanA_kernel<<<(BB * NCHUNK * HH / 2) / 256, 256>>>();
    scanB_kernel<<<(BB * HH * 32) / 256, 256>>>();
    scanC_kernel<<<(BB * NCHUNK * HH / 2) / 256, 256>>>(x, out);
}

// round 12
// speedup vs baseline: 1.0524x; 1.0044x over previous
#include <cuda_runtime.h>
#include <cuda_fp16.h>
#include <cstdint>
#include <math.h>

// Problem dims (fixed by reference setup_inputs)
#define BB 4
#define TT 4096
#define HH 1024
#define M_TOTAL (BB*TT)      // 16384
#define NCHUNK 64
#define CHUNK (TT/NCHUNK)    // 64

// Scratch (allocation-free rule: __device__ globals)
__device__ __half g_normh[(size_t)M_TOTAL*HH];   // fp16 LN output (32MB)
__device__ __half g_Wh[(size_t)2*HH*HH];         // fp16 [Wg; Wc] (4MB)
__device__ __half g_zh[(size_t)M_TOTAL*HH];      // fp16 gate (32MB)
__device__ __half g_ch[(size_t)M_TOTAL*HH];      // fp16 candidate (32MB)
__device__ float g_P[BB*NCHUNK*HH];
__device__ float g_S[BB*NCHUNK*HH];
__device__ float g_hin[BB*NCHUNK*HH];

__device__ __forceinline__ uint32_t smem_u32(const void* p) {
    uint32_t a;
    asm("{ .reg .u64 t; cvta.to.shared.u64 t, %1; cvt.u32.u64 %0, t; }" : "=r"(a) : "l"(p));
    return a;
}
__device__ __forceinline__ void cp16(uint32_t dst, const void* src) {
    asm volatile("cp.async.cg.shared.global [%0], [%1], 16;" :: "r"(dst), "l"(src));
}

// ---------------------------------------------------------------------------
// Kernel 0: convert Wg/Wc to fp16 into g_Wh
// ---------------------------------------------------------------------------
__global__ void halfW_kernel(const float* __restrict__ Wg,
                             const float* __restrict__ Wc) {
    int i = blockIdx.x * blockDim.x + threadIdx.x;   // over 2*HH*HH/4
    int half_n = HH * HH / 4;
    const float4* src = (i < half_n) ? (const float4*)Wg : (const float4*)Wc;
    float4 v = src[(i < half_n) ? i : (i - half_n)];
    __half2 h0 = __floats2half2_rn(v.x, v.y);
    __half2 h1 = __floats2half2_rn(v.z, v.w);
    ((uint2*)g_Wh)[i] = make_uint2(*(uint32_t*)&h0, *(uint32_t*)&h1);
}

// ---------------------------------------------------------------------------
// Kernel 1: LayerNorm -> fp16 normed. Warp-per-row (8 rows/block), pure
// shfl reduction, 8 float4/lane in flight, no block barrier.
// ---------------------------------------------------------------------------
__global__ __launch_bounds__(256) void ln_kernel(
    const float* __restrict__ x,
    const float* __restrict__ gamma,
    const float* __restrict__ beta) {
    int warp = threadIdx.x >> 5, lane = threadIdx.x & 31;
    int row = blockIdx.x * 8 + warp;
    const float4* xr = (const float4*)(x + (size_t)row * HH);

    float4 v[8];
    float s = 0.f, s2 = 0.f;
    #pragma unroll
    for (int q = 0; q < 8; q++) {
        v[q] = xr[lane + 32 * q];
        s  += v[q].x + v[q].y + v[q].z + v[q].w;
        s2 += v[q].x*v[q].x + v[q].y*v[q].y + v[q].z*v[q].z + v[q].w*v[q].w;
    }
    #pragma unroll
    for (int o = 16; o > 0; o >>= 1) {
        s  += __shfl_xor_sync(0xFFFFFFFFu, s,  o);
        s2 += __shfl_xor_sync(0xFFFFFFFFu, s2, o);
    }
    float mu  = s * (1.f / HH);
    float var = s2 * (1.f / HH) - mu * mu;
    float rs  = rsqrtf(var + 1e-5f);

    uint2* orow = (uint2*)g_normh + (size_t)row * (HH / 4);
    #pragma unroll
    for (int q = 0; q < 8; q++) {
        int f = lane + 32 * q;
        float4 g  = ((const float4*)gamma)[f];
        float4 bt = ((const float4*)beta)[f];
        __half2 h0 = __floats2half2_rn((v[q].x - mu) * rs * g.x + bt.x,
                                       (v[q].y - mu) * rs * g.y + bt.y);
        __half2 h1 = __floats2half2_rn((v[q].z - mu) * rs * g.z + bt.z,
                                       (v[q].w - mu) * rs * g.w + bt.w);
        orow[f] = make_uint2(*(uint32_t*)&h0, *(uint32_t*)&h1);
    }
}

// ---------------------------------------------------------------------------
// Kernel 2: fp16 mma.sync (m16n8k16) GEMM, cp.async 4-stage pipeline,
// ldmatrix fragment loads. Block tile 128x128, BK=32, 4 warps (128 thr),
// warp tile 64x64 (2x2 warp grid). 2 CTAs/SM. At the mma.sync HMMA ceiling.
// Logical N = 2048: bn<8 -> Wg+sigmoid -> g_zh, bn>=8 -> g_ch.
// ---------------------------------------------------------------------------
#define BM 128
#define BN 128
#define BK 32                            // halves per K-tile
#define STAGES 4
#define SSTR_H 40                        // halves per smem row (80B: ldmatrix conflict-free)
#define A_STAGE_H (BM*SSTR_H)            // 5120 halves
#define B_STAGE_H (BN*SSTR_H)
#define GEMM_SMEM (STAGES*(A_STAGE_H+B_STAGE_H)*2)   // 81920 B

__global__ __launch_bounds__(128, 2) void gemm_kernel(
    const float* __restrict__ bg, const float* __restrict__ bc)
{
    extern __shared__ __half smh[];
    uint32_t sA_u = smem_u32(smh);
    uint32_t sB_u = sA_u + STAGES * A_STAGE_H * 2;

    int tid = threadIdx.x;               // 128
    int warp = tid >> 5, lane = tid & 31;
    int bn = blockIdx.x;                 // 0..15 (fast -> wave shares A in L2)
    int bm = blockIdx.y;                 // 0..127
    int wm = (warp & 1) * 64;            // 2 M-warps
    int wn = (warp >> 1) * 64;           // 2 N-warps

    bool isGate = (bn < 8);
    size_t woff = isGate ? 0 : (size_t)HH * HH;
    int nbase = (bn & 7) * BN;
    size_t arow = (size_t)bm * BM;

    const __half* Asrc0 = g_normh + arow * HH;
    const __half* Bsrc0 = g_Wh + woff + (size_t)nbase * HH;

    float acc[4][8][4];                  // 4 m16 x 8 n8 x 4 regs
    #pragma unroll
    for (int i = 0; i < 4; i++)
        #pragma unroll
        for (int j = 0; j < 8; j++)
            #pragma unroll
            for (int q = 0; q < 4; q++) acc[i][j][q] = 0.f;

    // loads: per stage A 512 + B 512 16B-chunks, 128 thr -> 4+4 each
    int lr[4], lc[4];
    #pragma unroll
    for (int q = 0; q < 4; q++) {
        int f = tid + q * 128;
        lr[q] = f >> 2;                  // row 0..127
        lc[q] = (f & 3) * 8;             // half offset in row (16B chunks)
    }

    #define LOAD_STAGE(s, k0) do { \
        uint32_t abase = sA_u + (uint32_t)(s) * A_STAGE_H * 2; \
        uint32_t bbase = sB_u + (uint32_t)(s) * B_STAGE_H * 2; \
        _Pragma("unroll") \
        for (int q = 0; q < 4; q++) { \
            cp16(abase + (uint32_t)(lr[q] * SSTR_H + lc[q]) * 2, \
                 Asrc0 + (size_t)lr[q] * HH + (k0) + lc[q]); \
            cp16(bbase + (uint32_t)(lr[q] * SSTR_H + lc[q]) * 2, \
                 Bsrc0 + (size_t)lr[q] * HH + (k0) + lc[q]); \
        } \
    } while (0)

    LOAD_STAGE(0, 0);
    asm volatile("cp.async.commit_group;");
    LOAD_STAGE(1, BK);
    asm volatile("cp.async.commit_group;");
    LOAD_STAGE(2, 2 * BK);
    asm volatile("cp.async.commit_group;");

    // per-lane ldmatrix address components (bytes)
    uint32_t a_row = (uint32_t)(lane & 15);          // row within m16
    uint32_t a_kb  = ((lane >> 4) & 1) * 16;         // +8 halves
    uint32_t b_row = (uint32_t)((lane & 7) + ((lane >> 4) & 1) * 8);  // row within n16
    uint32_t b_kb  = ((lane >> 3) & 1) * 16;

    const int NK = HH / BK;              // 32
    for (int i = 0; i < NK; i++) {
        int s = i & (STAGES - 1);
        asm volatile("cp.async.wait_group 2;");
        __syncthreads();
        if (i + 3 < NK) {
            int s2 = (i + 3) & (STAGES - 1);
            LOAD_STAGE(s2, (i + 3) * BK);
        }
        asm volatile("cp.async.commit_group;");

        uint32_t abase = sA_u + (uint32_t)s * A_STAGE_H * 2;
        uint32_t bbase = sB_u + (uint32_t)s * B_STAGE_H * 2;

        #pragma unroll
        for (int ks = 0; ks < 2; ks++) {     // two k16 steps per K-tile
            unsigned af[4][4];
            #pragma unroll
            for (int ii = 0; ii < 4; ii++) {
                uint32_t addr = abase + (wm + ii * 16 + a_row) * (SSTR_H * 2)
                                + ks * 32 + a_kb;
                asm volatile(
                    "ldmatrix.sync.aligned.m8n8.x4.shared.b16 {%0,%1,%2,%3}, [%4];"
                    : "=r"(af[ii][0]), "=r"(af[ii][1]), "=r"(af[ii][2]), "=r"(af[ii][3])
                    : "r"(addr));
            }
            unsigned bf[8][2];
            #pragma unroll
            for (int j2 = 0; j2 < 4; j2++) {  // each x4 covers two n8 subtiles
                uint32_t addr = bbase + (wn + j2 * 16 + b_row) * (SSTR_H * 2)
                                + ks * 32 + b_kb;
                asm volatile(
                    "ldmatrix.sync.aligned.m8n8.x4.shared.b16 {%0,%1,%2,%3}, [%4];"
                    : "=r"(bf[j2*2][0]), "=r"(bf[j2*2][1]),
                      "=r"(bf[j2*2+1][0]), "=r"(bf[j2*2+1][1])
                    : "r"(addr));
            }
            #pragma unroll
            for (int ii = 0; ii < 4; ii++) {
                #pragma unroll
                for (int j = 0; j < 8; j++) {
                    float* a4 = acc[ii][j];
                    asm volatile(
                        "mma.sync.aligned.m16n8k16.row.col.f32.f16.f16.f32 "
                        "{%0,%1,%2,%3},{%4,%5,%6,%7},{%8,%9},{%0,%1,%2,%3};"
                        : "+f"(a4[0]), "+f"(a4[1]), "+f"(a4[2]), "+f"(a4[3])
                        : "r"(af[ii][0]), "r"(af[ii][1]), "r"(af[ii][2]), "r"(af[ii][3]),
                          "r"(bf[j][0]), "r"(bf[j][1]));
                }
            }
        }
    }
    asm volatile("cp.async.wait_group 0;");

    // Epilogue: +bias, optional sigmoid, write z or c as fp16
    int r  = lane >> 2;
    int cq = (lane & 3) * 2;
    const float* bias = isGate ? bg : bc;
    __half* outp = isGate ? g_zh : g_ch;
    #pragma unroll
    for (int ii = 0; ii < 4; ii++) {
        #pragma unroll
        for (int j = 0; j < 8; j++) {
            float* a4 = acc[ii][j];
            int m0 = bm * BM + wm + ii * 16 + r;
            int n0 = nbase + wn + j * 8 + cq;
            float b0 = bias[n0], b1 = bias[n0 + 1];
            float v0 = a4[0] + b0;
            float v1 = a4[1] + b1;
            float v2 = a4[2] + b0;
            float v3 = a4[3] + b1;
            if (isGate) {
                v0 = 1.f / (1.f + __expf(-v0));
                v1 = 1.f / (1.f + __expf(-v1));
                v2 = 1.f / (1.f + __expf(-v2));
                v3 = 1.f / (1.f + __expf(-v3));
            }
            *(__half2*)(outp + (size_t)m0 * HH + n0)       = __floats2half2_rn(v0, v1);
            *(__half2*)(outp + (size_t)(m0 + 8) * HH + n0) = __floats2half2_rn(v2, v3);
        }
    }
}

// ---------------------------------------------------------------------------
// Scan phase A: per-(b, chunk, hid) aggregates. 4 hids/thread via uint2
// (8B loads from each of z,c; float4 state) -> more bytes in flight.
// ---------------------------------------------------------------------------
__global__ void scanA_kernel() {
    int g4  = blockIdx.x * blockDim.x + threadIdx.x;   // over BB*NCHUNK*HH/4
    int hq  = g4 % (HH / 4);
    int ck  = (g4 / (HH / 4)) % NCHUNK;
    int b   = g4 / ((HH / 4) * NCHUNK);
    size_t base = ((size_t)(b * TT + ck * CHUNK)) * HH + 4 * hq;
    float4 P = make_float4(1.f, 1.f, 1.f, 1.f);
    float4 S = make_float4(0.f, 0.f, 0.f, 0.f);
    #pragma unroll 4
    for (int t = 0; t < CHUNK; t++) {
        size_t idx = base + (size_t)t * HH;
        uint2 zu = *(const uint2*)(g_zh + idx);
        uint2 cu = *(const uint2*)(g_ch + idx);
        float2 z0 = __half22float2(*(__half2*)&zu.x);
        float2 z1 = __half22float2(*(__half2*)&zu.y);
        float2 c0 = __half22float2(*(__half2*)&cu.x);
        float2 c1 = __half22float2(*(__half2*)&cu.y);
        float a0 = 1.f - z0.x, a1 = 1.f - z0.y, a2 = 1.f - z1.x, a3 = 1.f - z1.y;
        S.x = a0 * S.x + z0.x * c0.x;  P.x *= a0;
        S.y = a1 * S.y + z0.y * c0.y;  P.y *= a1;
        S.z = a2 * S.z + z1.x * c1.x;  P.z *= a2;
        S.w = a3 * S.w + z1.y * c1.y;  P.w *= a3;
    }
    size_t o = ((size_t)(b * NCHUNK + ck)) * (HH / 4) + hq;
    ((float4*)g_P)[o] = P;
    ((float4*)g_S)[o] = S;
}

// ---------------------------------------------------------------------------
// Scan phase B: parallel Kogge-Stone over 64 chunk aggregates per (b,hid).
// ---------------------------------------------------------------------------
__global__ void scanB_kernel() {
    int gt   = blockIdx.x * blockDim.x + threadIdx.x;
    int lane = gt & 31;
    int wg   = gt >> 5;                 // 0..BB*HH-1
    int hid  = wg & (HH - 1);
    int b    = wg >> 10;                // HH = 1024
    int k0   = 2 * lane;
    size_t i0 = ((size_t)(b * NCHUNK + k0)) * HH + hid;
    float P0 = g_P[i0],      S0 = g_S[i0];
    float P1 = g_P[i0 + HH], S1 = g_S[i0 + HH];
    float cP = P1 * P0;
    float cS = P1 * S0 + S1;
    #pragma unroll
    for (int d = 1; d < 32; d <<= 1) {
        float pP = __shfl_up_sync(0xFFFFFFFFu, cP, d);
        float pS = __shfl_up_sync(0xFFFFFFFFu, cS, d);
        if (lane >= d) { cS = cP * pS + cS; cP = cP * pP; }
    }
    float eS = __shfl_up_sync(0xFFFFFFFFu, cS, 1);
    if (lane == 0) eS = 0.f;
    g_hin[i0]      = eS;
    g_hin[i0 + HH] = P0 * eS + S0;
}

// ---------------------------------------------------------------------------
// Scan phase C: re-run each chunk with the correct h_in, fuse residual +x.
// 4 hids/thread: 8B z + 8B c + 16B x loads, 16B store per t-step.
// ---------------------------------------------------------------------------
__global__ void scanC_kernel(const float* __restrict__ x, float* __restrict__ out) {
    int g4  = blockIdx.x * blockDim.x + threadIdx.x;   // over BB*NCHUNK*HH/4
    int hq  = g4 % (HH / 4);
    int ck  = (g4 / (HH / 4)) % NCHUNK;
    int b   = g4 / ((HH / 4) * NCHUNK);
    size_t base = ((size_t)(b * TT + ck * CHUNK)) * HH + 4 * hq;
    float4 h = ((const float4*)g_hin)[((size_t)(b * NCHUNK + ck)) * (HH / 4) + hq];
    #pragma unroll 4
    for (int t = 0; t < CHUNK; t++) {
        size_t idx = base + (size_t)t * HH;
        uint2 zu = *(const uint2*)(g_zh + idx);
        uint2 cu = *(const uint2*)(g_ch + idx);
        float2 z0 = __half22float2(*(__half2*)&zu.x);
        float2 z1 = __half22float2(*(__half2*)&zu.y);
        float2 c0 = __half22float2(*(__half2*)&cu.x);
        float2 c1 = __half22float2(*(__half2*)&cu.y);
        h.x = (1.f - z0.x) * h.x + z0.x * c0.x;
        h.y = (1.f - z0.y) * h.y + z0.y * c0.y;
        h.z = (1.f - z1.x) * h.z + z1.x * c1.x;
        h.w = (1.f - z1.y) * h.w + z1.y * c1.y;
        float4 xv = *(const float4*)(x + idx);
        *(float4*)(out + idx) = make_float4(h.x + xv.x, h.y + xv.y,
                                            h.z + xv.z, h.w + xv.w);
    }
}

// ---------------------------------------------------------------------------
extern "C" void kernel_launch(void* const* d_in, const int* in_sizes, int n_in,
                              void* d_out, int out_size) {
    const float* x     = (const float*)d_in[0];
    const float* gamma = (const float*)d_in[1];
    const float* beta  = (const float*)d_in[2];
    const float* Wg    = (const float*)d_in[3];
    const float* bg    = (const float*)d_in[4];
    const float* Wc    = (const float*)d_in[5];
    const float* bc    = (const float*)d_in[6];
    float* out = (float*)d_out;

    halfW_kernel<<<(2 * HH * HH / 4) / 256, 256>>>(Wg, Wc);
    ln_kernel<<<M_TOTAL / 8, 256>>>(x, gamma, beta);

    cudaFuncSetAttribute(gemm_kernel,
                         cudaFuncAttributeMaxDynamicSharedMemorySize, GEMM_SMEM);
    dim3 ggrid(2 * HH / BN, M_TOTAL / BM);   // (16, 128)
    gemm_kernel<<<ggrid, 128, GEMM_SMEM>>>(bg, bc);

    scanA_kernel<<<(BB * NCHUNK * HH / 4) / 256, 256>>>();
    scanB_kernel<<<(BB * HH * 32) / 256, 256>>>();
    scanC_kernel<<<(BB * NCHUNK * HH / 4) / 256, 256>>>(x, out);
}

// round 13
// speedup vs baseline: 1.1266x; 1.0706x over previous
#include <cuda_runtime.h>
#include <cuda_fp16.h>
#include <cstdint>
#include <math.h>

// Problem dims (fixed by reference setup_inputs)
#define BB 4
#define TT 4096
#define HH 1024
#define M_TOTAL (BB*TT)      // 16384
#define NCHUNK 128
#define CHUNK (TT/NCHUNK)    // 32

// Scratch (allocation-free rule: __device__ globals)
__device__ __half g_normh[(size_t)M_TOTAL*HH];   // fp16 LN output (32MB)
__device__ __half g_Wh[(size_t)2*HH*HH];         // fp16 [Wg; Wc] (4MB)
__device__ __half g_zh[(size_t)M_TOTAL*HH];      // fp16 gate (32MB)
__device__ __half g_ch[(size_t)M_TOTAL*HH];      // fp16 candidate (32MB)
__device__ float g_P[(size_t)BB*NCHUNK*HH];
__device__ float g_S[(size_t)BB*NCHUNK*HH];
__device__ float g_hin[(size_t)BB*NCHUNK*HH];

__device__ __forceinline__ uint32_t smem_u32(const void* p) {
    uint32_t a;
    asm("{ .reg .u64 t; cvta.to.shared.u64 t, %1; cvt.u32.u64 %0, t; }" : "=r"(a) : "l"(p));
    return a;
}
__device__ __forceinline__ void cp16(uint32_t dst, const void* src) {
    asm volatile("cp.async.cg.shared.global [%0], [%1], 16;" :: "r"(dst), "l"(src));
}

// ---------------------------------------------------------------------------
// Kernel 0: convert Wg/Wc to fp16 into g_Wh
// ---------------------------------------------------------------------------
__global__ void halfW_kernel(const float* __restrict__ Wg,
                             const float* __restrict__ Wc) {
    int i = blockIdx.x * blockDim.x + threadIdx.x;   // over 2*HH*HH/4
    int half_n = HH * HH / 4;
    const float4* src = (i < half_n) ? (const float4*)Wg : (const float4*)Wc;
    float4 v = src[(i < half_n) ? i : (i - half_n)];
    __half2 h0 = __floats2half2_rn(v.x, v.y);
    __half2 h1 = __floats2half2_rn(v.z, v.w);
    ((uint2*)g_Wh)[i] = make_uint2(*(uint32_t*)&h0, *(uint32_t*)&h1);
}

// ---------------------------------------------------------------------------
// Kernel 1: LayerNorm -> fp16 normed. Warp-per-row (8 rows/block), pure
// shfl reduction, 8 float4/lane in flight, no block barrier.
// ---------------------------------------------------------------------------
__global__ __launch_bounds__(256) void ln_kernel(
    const float* __restrict__ x,
    const float* __restrict__ gamma,
    const float* __restrict__ beta) {
    int warp = threadIdx.x >> 5, lane = threadIdx.x & 31;
    int row = blockIdx.x * 8 + warp;
    const float4* xr = (const float4*)(x + (size_t)row * HH);

    float4 v[8];
    float s = 0.f, s2 = 0.f;
    #pragma unroll
    for (int q = 0; q < 8; q++) {
        v[q] = xr[lane + 32 * q];
        s  += v[q].x + v[q].y + v[q].z + v[q].w;
        s2 += v[q].x*v[q].x + v[q].y*v[q].y + v[q].z*v[q].z + v[q].w*v[q].w;
    }
    #pragma unroll
    for (int o = 16; o > 0; o >>= 1) {
        s  += __shfl_xor_sync(0xFFFFFFFFu, s,  o);
        s2 += __shfl_xor_sync(0xFFFFFFFFu, s2, o);
    }
    float mu  = s * (1.f / HH);
    float var = s2 * (1.f / HH) - mu * mu;
    float rs  = rsqrtf(var + 1e-5f);

    uint2* orow = (uint2*)g_normh + (size_t)row * (HH / 4);
    #pragma unroll
    for (int q = 0; q < 8; q++) {
        int f = lane + 32 * q;
        float4 g  = ((const float4*)gamma)[f];
        float4 bt = ((const float4*)beta)[f];
        __half2 h0 = __floats2half2_rn((v[q].x - mu) * rs * g.x + bt.x,
                                       (v[q].y - mu) * rs * g.y + bt.y);
        __half2 h1 = __floats2half2_rn((v[q].z - mu) * rs * g.z + bt.z,
                                       (v[q].w - mu) * rs * g.w + bt.w);
        orow[f] = make_uint2(*(uint32_t*)&h0, *(uint32_t*)&h1);
    }
}

// ---------------------------------------------------------------------------
// Kernel 2: fp16 mma.sync (m16n8k16) GEMM, cp.async 4-stage pipeline,
// ldmatrix fragment loads. Block tile 128x128, BK=32, 4 warps (128 thr),
// warp tile 64x64 (2x2 warp grid). 2 CTAs/SM. At the mma.sync HMMA ceiling.
// Logical N = 2048: bn<8 -> Wg+sigmoid -> g_zh, bn>=8 -> g_ch.
// ---------------------------------------------------------------------------
#define BM 128
#define BN 128
#define BK 32                            // halves per K-tile
#define STAGES 4
#define SSTR_H 40                        // halves per smem row (80B: ldmatrix conflict-free)
#define A_STAGE_H (BM*SSTR_H)            // 5120 halves
#define B_STAGE_H (BN*SSTR_H)
#define GEMM_SMEM (STAGES*(A_STAGE_H+B_STAGE_H)*2)   // 81920 B

__global__ __launch_bounds__(128, 2) void gemm_kernel(
    const float* __restrict__ bg, const float* __restrict__ bc)
{
    extern __shared__ __half smh[];
    uint32_t sA_u = smem_u32(smh);
    uint32_t sB_u = sA_u + STAGES * A_STAGE_H * 2;

    int tid = threadIdx.x;               // 128
    int warp = tid >> 5, lane = tid & 31;
    int bn = blockIdx.x;                 // 0..15 (fast -> wave shares A in L2)
    int bm = blockIdx.y;                 // 0..127
    int wm = (warp & 1) * 64;            // 2 M-warps
    int wn = (warp >> 1) * 64;           // 2 N-warps

    bool isGate = (bn < 8);
    size_t woff = isGate ? 0 : (size_t)HH * HH;
    int nbase = (bn & 7) * BN;
    size_t arow = (size_t)bm * BM;

    const __half* Asrc0 = g_normh + arow * HH;
    const __half* Bsrc0 = g_Wh + woff + (size_t)nbase * HH;

    float acc[4][8][4];                  // 4 m16 x 8 n8 x 4 regs
    #pragma unroll
    for (int i = 0; i < 4; i++)
        #pragma unroll
        for (int j = 0; j < 8; j++)
            #pragma unroll
            for (int q = 0; q < 4; q++) acc[i][j][q] = 0.f;

    // loads: per stage A 512 + B 512 16B-chunks, 128 thr -> 4+4 each
    int lr[4], lc[4];
    #pragma unroll
    for (int q = 0; q < 4; q++) {
        int f = tid + q * 128;
        lr[q] = f >> 2;                  // row 0..127
        lc[q] = (f & 3) * 8;             // half offset in row (16B chunks)
    }

    #define LOAD_STAGE(s, k0) do { \
        uint32_t abase = sA_u + (uint32_t)(s) * A_STAGE_H * 2; \
        uint32_t bbase = sB_u + (uint32_t)(s) * B_STAGE_H * 2; \
        _Pragma("unroll") \
        for (int q = 0; q < 4; q++) { \
            cp16(abase + (uint32_t)(lr[q] * SSTR_H + lc[q]) * 2, \
                 Asrc0 + (size_t)lr[q] * HH + (k0) + lc[q]); \
            cp16(bbase + (uint32_t)(lr[q] * SSTR_H + lc[q]) * 2, \
                 Bsrc0 + (size_t)lr[q] * HH + (k0) + lc[q]); \
        } \
    } while (0)

    LOAD_STAGE(0, 0);
    asm volatile("cp.async.commit_group;");
    LOAD_STAGE(1, BK);
    asm volatile("cp.async.commit_group;");
    LOAD_STAGE(2, 2 * BK);
    asm volatile("cp.async.commit_group;");

    // per-lane ldmatrix address components (bytes)
    uint32_t a_row = (uint32_t)(lane & 15);          // row within m16
    uint32_t a_kb  = ((lane >> 4) & 1) * 16;         // +8 halves
    uint32_t b_row = (uint32_t)((lane & 7) + ((lane >> 4) & 1) * 8);  // row within n16
    uint32_t b_kb  = ((lane >> 3) & 1) * 16;

    const int NK = HH / BK;              // 32
    for (int i = 0; i < NK; i++) {
        int s = i & (STAGES - 1);
        asm volatile("cp.async.wait_group 2;");
        __syncthreads();
        if (i + 3 < NK) {
            int s2 = (i + 3) & (STAGES - 1);
            LOAD_STAGE(s2, (i + 3) * BK);
        }
        asm volatile("cp.async.commit_group;");

        uint32_t abase = sA_u + (uint32_t)s * A_STAGE_H * 2;
        uint32_t bbase = sB_u + (uint32_t)s * B_STAGE_H * 2;

        #pragma unroll
        for (int ks = 0; ks < 2; ks++) {     // two k16 steps per K-tile
            unsigned af[4][4];
            #pragma unroll
            for (int ii = 0; ii < 4; ii++) {
                uint32_t addr = abase + (wm + ii * 16 + a_row) * (SSTR_H * 2)
                                + ks * 32 + a_kb;
                asm volatile(
                    "ldmatrix.sync.aligned.m8n8.x4.shared.b16 {%0,%1,%2,%3}, [%4];"
                    : "=r"(af[ii][0]), "=r"(af[ii][1]), "=r"(af[ii][2]), "=r"(af[ii][3])
                    : "r"(addr));
            }
            unsigned bf[8][2];
            #pragma unroll
            for (int j2 = 0; j2 < 4; j2++) {  // each x4 covers two n8 subtiles
                uint32_t addr = bbase + (wn + j2 * 16 + b_row) * (SSTR_H * 2)
                                + ks * 32 + b_kb;
                asm volatile(
                    "ldmatrix.sync.aligned.m8n8.x4.shared.b16 {%0,%1,%2,%3}, [%4];"
                    : "=r"(bf[j2*2][0]), "=r"(bf[j2*2][1]),
                      "=r"(bf[j2*2+1][0]), "=r"(bf[j2*2+1][1])
                    : "r"(addr));
            }
            #pragma unroll
            for (int ii = 0; ii < 4; ii++) {
                #pragma unroll
                for (int j = 0; j < 8; j++) {
                    float* a4 = acc[ii][j];
                    asm volatile(
                        "mma.sync.aligned.m16n8k16.row.col.f32.f16.f16.f32 "
                        "{%0,%1,%2,%3},{%4,%5,%6,%7},{%8,%9},{%0,%1,%2,%3};"
                        : "+f"(a4[0]), "+f"(a4[1]), "+f"(a4[2]), "+f"(a4[3])
                        : "r"(af[ii][0]), "r"(af[ii][1]), "r"(af[ii][2]), "r"(af[ii][3]),
                          "r"(bf[j][0]), "r"(bf[j][1]));
                }
            }
        }
    }
    asm volatile("cp.async.wait_group 0;");

    // Epilogue: +bias, optional sigmoid, write z or c as fp16
    int r  = lane >> 2;
    int cq = (lane & 3) * 2;
    const float* bias = isGate ? bg : bc;
    __half* outp = isGate ? g_zh : g_ch;
    #pragma unroll
    for (int ii = 0; ii < 4; ii++) {
        #pragma unroll
        for (int j = 0; j < 8; j++) {
            float* a4 = acc[ii][j];
            int m0 = bm * BM + wm + ii * 16 + r;
            int n0 = nbase + wn + j * 8 + cq;
            float b0 = bias[n0], b1 = bias[n0 + 1];
            float v0 = a4[0] + b0;
            float v1 = a4[1] + b1;
            float v2 = a4[2] + b0;
            float v3 = a4[3] + b1;
            if (isGate) {
                v0 = 1.f / (1.f + __expf(-v0));
                v1 = 1.f / (1.f + __expf(-v1));
                v2 = 1.f / (1.f + __expf(-v2));
                v3 = 1.f / (1.f + __expf(-v3));
            }
            *(__half2*)(outp + (size_t)m0 * HH + n0)       = __floats2half2_rn(v0, v1);
            *(__half2*)(outp + (size_t)(m0 + 8) * HH + n0) = __floats2half2_rn(v2, v3);
        }
    }
}

// ---------------------------------------------------------------------------
// Scan phase A: per-(b, chunk, hid) aggregates. 2 hids/thread via half2,
// CHUNK=32 -> 1024 CTAs (2x parallelism vs R9).
// ---------------------------------------------------------------------------
__global__ void scanA_kernel() {
    int g2  = blockIdx.x * blockDim.x + threadIdx.x;   // over BB*NCHUNK*HH/2
    int hp  = g2 % (HH / 2);
    int ck  = (g2 / (HH / 2)) % NCHUNK;
    int b   = g2 / ((HH / 2) * NCHUNK);
    size_t base = ((size_t)(b * TT + ck * CHUNK)) * HH + 2 * hp;
    float2 P = make_float2(1.f, 1.f), S = make_float2(0.f, 0.f);
    #pragma unroll 8
    for (int t = 0; t < CHUNK; t++) {
        size_t idx = base + (size_t)t * HH;
        float2 z = __half22float2(*(const __half2*)(g_zh + idx));
        float2 c = __half22float2(*(const __half2*)(g_ch + idx));
        float ax = 1.f - z.x, ay = 1.f - z.y;
        S.x = ax * S.x + z.x * c.x;  P.x *= ax;
        S.y = ay * S.y + z.y * c.y;  P.y *= ay;
    }
    size_t o = ((size_t)(b * NCHUNK + ck)) * (HH / 2) + hp;
    ((float2*)g_P)[o] = P;
    ((float2*)g_S)[o] = S;
}

// ---------------------------------------------------------------------------
// Scan phase B: Kogge-Stone over 128 chunk aggregates per (b, hid-pair).
// One warp per (b,hp); float2 lanes, each lane composes 4 consecutive
// chunks (coalesced 8B loads), 5-step shfl scan, emits 4 h_in float2.
// ---------------------------------------------------------------------------
__global__ void scanB_kernel() {
    int gt   = blockIdx.x * blockDim.x + threadIdx.x;
    int lane = gt & 31;
    int wg   = gt >> 5;                 // 0..BB*HH/2-1
    int hp   = wg & (HH / 2 - 1);
    int b    = wg >> 9;                 // HH/2 = 512
    int k0   = 4 * lane;
    const float2* P2 = (const float2*)g_P;
    const float2* S2 = (const float2*)g_S;
    size_t i0 = ((size_t)(b * NCHUNK + k0)) * (HH / 2) + hp;
    float2 Pk[4], Sk[4];
    #pragma unroll
    for (int q = 0; q < 4; q++) {
        Pk[q] = P2[i0 + (size_t)q * (HH / 2)];
        Sk[q] = S2[i0 + (size_t)q * (HH / 2)];
    }
    float2 cP = Pk[0], cS = Sk[0];
    #pragma unroll
    for (int q = 1; q < 4; q++) {
        cS.x = Pk[q].x * cS.x + Sk[q].x;  cP.x *= Pk[q].x;
        cS.y = Pk[q].y * cS.y + Sk[q].y;  cP.y *= Pk[q].y;
    }
    #pragma unroll
    for (int d = 1; d < 32; d <<= 1) {
        float pPx = __shfl_up_sync(0xFFFFFFFFu, cP.x, d);
        float pPy = __shfl_up_sync(0xFFFFFFFFu, cP.y, d);
        float pSx = __shfl_up_sync(0xFFFFFFFFu, cS.x, d);
        float pSy = __shfl_up_sync(0xFFFFFFFFu, cS.y, d);
        if (lane >= d) {
            cS.x = cP.x * pSx + cS.x;  cP.x = cP.x * pPx;
            cS.y = cP.y * pSy + cS.y;  cP.y = cP.y * pPy;
        }
    }
    float2 h;
    h.x = __shfl_up_sync(0xFFFFFFFFu, cS.x, 1);
    h.y = __shfl_up_sync(0xFFFFFFFFu, cS.y, 1);
    if (lane == 0) { h.x = 0.f; h.y = 0.f; }
    float2* H2 = (float2*)g_hin;
    #pragma unroll
    for (int q = 0; q < 4; q++) {
        size_t idx = i0 + (size_t)q * (HH / 2);
        H2[idx] = h;
        h.x = Pk[q].x * h.x + Sk[q].x;
        h.y = Pk[q].y * h.y + Sk[q].y;
    }
}

// ---------------------------------------------------------------------------
// Scan phase C: re-run each chunk with the correct h_in, fuse residual +x.
// 2 hids/thread; CHUNK=32 -> 1024 CTAs.
// ---------------------------------------------------------------------------
__global__ void scanC_kernel(const float* __restrict__ x, float* __restrict__ out) {
    int g2  = blockIdx.x * blockDim.x + threadIdx.x;   // over BB*NCHUNK*HH/2
    int hp  = g2 % (HH / 2);
    int ck  = (g2 / (HH / 2)) % NCHUNK;
    int b   = g2 / ((HH / 2) * NCHUNK);
    size_t base = ((size_t)(b * TT + ck * CHUNK)) * HH + 2 * hp;
    float2 h = ((const float2*)g_hin)[((size_t)(b * NCHUNK + ck)) * (HH / 2) + hp];
    #pragma unroll 8
    for (int t = 0; t < CHUNK; t++) {
        size_t idx = base + (size_t)t * HH;
        float2 z = __half22float2(*(const __half2*)(g_zh + idx));
        float2 c = __half22float2(*(const __half2*)(g_ch + idx));
        h.x = (1.f - z.x) * h.x + z.x * c.x;
        h.y = (1.f - z.y) * h.y + z.y * c.y;
        float2 xv = *(const float2*)(x + idx);
        *(float2*)(out + idx) = make_float2(h.x + xv.x, h.y + xv.y);
    }
}

// ---------------------------------------------------------------------------
extern "C" void kernel_launch(void* const* d_in, const int* in_sizes, int n_in,
                              void* d_out, int out_size) {
    const float* x     = (const float*)d_in[0];
    const float* gamma = (const float*)d_in[1];
    const float* beta  = (const float*)d_in[2];
    const float* Wg    = (const float*)d_in[3];
    const float* bg    = (const float*)d_in[4];
    const float* Wc    = (const float*)d_in[5];
    const float* bc    = (const float*)d_in[6];
    float* out = (float*)d_out;

    halfW_kernel<<<(2 * HH * HH / 4) / 256, 256>>>(Wg, Wc);
    ln_kernel<<<M_TOTAL / 8, 256>>>(x, gamma, beta);

    cudaFuncSetAttribute(gemm_kernel,
                         cudaFuncAttributeMaxDynamicSharedMemorySize, GEMM_SMEM);
    dim3 ggrid(2 * HH / BN, M_TOTAL / BM);   // (16, 128)
    gemm_kernel<<<ggrid, 128, GEMM_SMEM>>>(bg, bc);

    scanA_kernel<<<(BB * NCHUNK * HH / 2) / 256, 256>>>();
    scanB_kernel<<<(BB * (HH / 2) * 32) / 256, 256>>>();
    scanC_kernel<<<(BB * NCHUNK * HH / 2) / 256, 256>>>(x, out);
}

// round 14
// speedup vs baseline: 1.1295x; 1.0025x over previous
#include <cuda_runtime.h>
#include <cuda_fp16.h>
#include <cstdint>
#include <math.h>

// Problem dims (fixed by reference setup_inputs)
#define BB 4
#define TT 4096
#define HH 1024
#define M_TOTAL (BB*TT)      // 16384
#define NCHUNK 128
#define CHUNK (TT/NCHUNK)    // 32

// Scratch (allocation-free rule: __device__ globals)
__device__ __half g_normh[(size_t)M_TOTAL*HH];   // fp16 LN output (32MB)
__device__ __half g_Wh[(size_t)2*HH*HH];         // fp16 [Wg; Wc] (4MB)
__device__ __half g_zh[(size_t)M_TOTAL*HH];      // fp16 gate (32MB)
__device__ __half g_ch[(size_t)M_TOTAL*HH];      // fp16 candidate (32MB)
__device__ float4 g_PS[(size_t)BB*NCHUNK*HH/2];  // interleaved (Px,Py,Sx,Sy) per hp (4MB)
__device__ float g_hin[(size_t)BB*NCHUNK*HH];

__device__ __forceinline__ uint32_t smem_u32(const void* p) {
    uint32_t a;
    asm("{ .reg .u64 t; cvta.to.shared.u64 t, %1; cvt.u32.u64 %0, t; }" : "=r"(a) : "l"(p));
    return a;
}
__device__ __forceinline__ void cp16(uint32_t dst, const void* src) {
    asm volatile("cp.async.cg.shared.global [%0], [%1], 16;" :: "r"(dst), "l"(src));
}

// ---------------------------------------------------------------------------
// Kernel 0: convert Wg/Wc to fp16 into g_Wh
// ---------------------------------------------------------------------------
__global__ void halfW_kernel(const float* __restrict__ Wg,
                             const float* __restrict__ Wc) {
    int i = blockIdx.x * blockDim.x + threadIdx.x;   // over 2*HH*HH/4
    int half_n = HH * HH / 4;
    const float4* src = (i < half_n) ? (const float4*)Wg : (const float4*)Wc;
    float4 v = src[(i < half_n) ? i : (i - half_n)];
    __half2 h0 = __floats2half2_rn(v.x, v.y);
    __half2 h1 = __floats2half2_rn(v.z, v.w);
    ((uint2*)g_Wh)[i] = make_uint2(*(uint32_t*)&h0, *(uint32_t*)&h1);
}

// ---------------------------------------------------------------------------
// Kernel 1: LayerNorm -> fp16 normed. Warp-per-row (8 rows/block), pure
// shfl reduction, 8 float4/lane in flight, no block barrier.
// ---------------------------------------------------------------------------
__global__ __launch_bounds__(256) void ln_kernel(
    const float* __restrict__ x,
    const float* __restrict__ gamma,
    const float* __restrict__ beta) {
    int warp = threadIdx.x >> 5, lane = threadIdx.x & 31;
    int row = blockIdx.x * 8 + warp;
    const float4* xr = (const float4*)(x + (size_t)row * HH);

    float4 v[8];
    float s = 0.f, s2 = 0.f;
    #pragma unroll
    for (int q = 0; q < 8; q++) {
        v[q] = xr[lane + 32 * q];
        s  += v[q].x + v[q].y + v[q].z + v[q].w;
        s2 += v[q].x*v[q].x + v[q].y*v[q].y + v[q].z*v[q].z + v[q].w*v[q].w;
    }
    #pragma unroll
    for (int o = 16; o > 0; o >>= 1) {
        s  += __shfl_xor_sync(0xFFFFFFFFu, s,  o);
        s2 += __shfl_xor_sync(0xFFFFFFFFu, s2, o);
    }
    float mu  = s * (1.f / HH);
    float var = s2 * (1.f / HH) - mu * mu;
    float rs  = rsqrtf(var + 1e-5f);

    uint2* orow = (uint2*)g_normh + (size_t)row * (HH / 4);
    #pragma unroll
    for (int q = 0; q < 8; q++) {
        int f = lane + 32 * q;
        float4 g  = ((const float4*)gamma)[f];
        float4 bt = ((const float4*)beta)[f];
        __half2 h0 = __floats2half2_rn((v[q].x - mu) * rs * g.x + bt.x,
                                       (v[q].y - mu) * rs * g.y + bt.y);
        __half2 h1 = __floats2half2_rn((v[q].z - mu) * rs * g.z + bt.z,
                                       (v[q].w - mu) * rs * g.w + bt.w);
        orow[f] = make_uint2(*(uint32_t*)&h0, *(uint32_t*)&h1);
    }
}

// ---------------------------------------------------------------------------
// Kernel 2: fp16 mma.sync (m16n8k16) GEMM, cp.async 4-stage pipeline,
// ldmatrix fragment loads. Block tile 128x128, BK=32, 4 warps (128 thr),
// warp tile 64x64 (2x2 warp grid). 2 CTAs/SM. At the mma.sync HMMA ceiling.
// Logical N = 2048: bn<8 -> Wg+sigmoid -> g_zh, bn>=8 -> g_ch.
// ---------------------------------------------------------------------------
#define BM 128
#define BN 128
#define BK 32                            // halves per K-tile
#define STAGES 4
#define SSTR_H 40                        // halves per smem row (80B: ldmatrix conflict-free)
#define A_STAGE_H (BM*SSTR_H)            // 5120 halves
#define B_STAGE_H (BN*SSTR_H)
#define GEMM_SMEM (STAGES*(A_STAGE_H+B_STAGE_H)*2)   // 81920 B

__global__ __launch_bounds__(128, 2) void gemm_kernel(
    const float* __restrict__ bg, const float* __restrict__ bc)
{
    extern __shared__ __half smh[];
    uint32_t sA_u = smem_u32(smh);
    uint32_t sB_u = sA_u + STAGES * A_STAGE_H * 2;

    int tid = threadIdx.x;               // 128
    int warp = tid >> 5, lane = tid & 31;
    int bn = blockIdx.x;                 // 0..15 (fast -> wave shares A in L2)
    int bm = blockIdx.y;                 // 0..127
    int wm = (warp & 1) * 64;            // 2 M-warps
    int wn = (warp >> 1) * 64;           // 2 N-warps

    bool isGate = (bn < 8);
    size_t woff = isGate ? 0 : (size_t)HH * HH;
    int nbase = (bn & 7) * BN;
    size_t arow = (size_t)bm * BM;

    const __half* Asrc0 = g_normh + arow * HH;
    const __half* Bsrc0 = g_Wh + woff + (size_t)nbase * HH;

    float acc[4][8][4];                  // 4 m16 x 8 n8 x 4 regs
    #pragma unroll
    for (int i = 0; i < 4; i++)
        #pragma unroll
        for (int j = 0; j < 8; j++)
            #pragma unroll
            for (int q = 0; q < 4; q++) acc[i][j][q] = 0.f;

    // loads: per stage A 512 + B 512 16B-chunks, 128 thr -> 4+4 each
    int lr[4], lc[4];
    #pragma unroll
    for (int q = 0; q < 4; q++) {
        int f = tid + q * 128;
        lr[q] = f >> 2;                  // row 0..127
        lc[q] = (f & 3) * 8;             // half offset in row (16B chunks)
    }

    #define LOAD_STAGE(s, k0) do { \
        uint32_t abase = sA_u + (uint32_t)(s) * A_STAGE_H * 2; \
        uint32_t bbase = sB_u + (uint32_t)(s) * B_STAGE_H * 2; \
        _Pragma("unroll") \
        for (int q = 0; q < 4; q++) { \
            cp16(abase + (uint32_t)(lr[q] * SSTR_H + lc[q]) * 2, \
                 Asrc0 + (size_t)lr[q] * HH + (k0) + lc[q]); \
            cp16(bbase + (uint32_t)(lr[q] * SSTR_H + lc[q]) * 2, \
                 Bsrc0 + (size_t)lr[q] * HH + (k0) + lc[q]); \
        } \
    } while (0)

    LOAD_STAGE(0, 0);
    asm volatile("cp.async.commit_group;");
    LOAD_STAGE(1, BK);
    asm volatile("cp.async.commit_group;");
    LOAD_STAGE(2, 2 * BK);
    asm volatile("cp.async.commit_group;");

    // per-lane ldmatrix address components (bytes)
    uint32_t a_row = (uint32_t)(lane & 15);          // row within m16
    uint32_t a_kb  = ((lane >> 4) & 1) * 16;         // +8 halves
    uint32_t b_row = (uint32_t)((lane & 7) + ((lane >> 4) & 1) * 8);  // row within n16
    uint32_t b_kb  = ((lane >> 3) & 1) * 16;

    const int NK = HH / BK;              // 32
    for (int i = 0; i < NK; i++) {
        int s = i & (STAGES - 1);
        asm volatile("cp.async.wait_group 2;");
        __syncthreads();
        if (i + 3 < NK) {
            int s2 = (i + 3) & (STAGES - 1);
            LOAD_STAGE(s2, (i + 3) * BK);
        }
        asm volatile("cp.async.commit_group;");

        uint32_t abase = sA_u + (uint32_t)s * A_STAGE_H * 2;
        uint32_t bbase = sB_u + (uint32_t)s * B_STAGE_H * 2;

        #pragma unroll
        for (int ks = 0; ks < 2; ks++) {     // two k16 steps per K-tile
            unsigned af[4][4];
            #pragma unroll
            for (int ii = 0; ii < 4; ii++) {
                uint32_t addr = abase + (wm + ii * 16 + a_row) * (SSTR_H * 2)
                                + ks * 32 + a_kb;
                asm volatile(
                    "ldmatrix.sync.aligned.m8n8.x4.shared.b16 {%0,%1,%2,%3}, [%4];"
                    : "=r"(af[ii][0]), "=r"(af[ii][1]), "=r"(af[ii][2]), "=r"(af[ii][3])
                    : "r"(addr));
            }
            unsigned bf[8][2];
            #pragma unroll
            for (int j2 = 0; j2 < 4; j2++) {  // each x4 covers two n8 subtiles
                uint32_t addr = bbase + (wn + j2 * 16 + b_row) * (SSTR_H * 2)
                                + ks * 32 + b_kb;
                asm volatile(
                    "ldmatrix.sync.aligned.m8n8.x4.shared.b16 {%0,%1,%2,%3}, [%4];"
                    : "=r"(bf[j2*2][0]), "=r"(bf[j2*2][1]),
                      "=r"(bf[j2*2+1][0]), "=r"(bf[j2*2+1][1])
                    : "r"(addr));
            }
            #pragma unroll
            for (int ii = 0; ii < 4; ii++) {
                #pragma unroll
                for (int j = 0; j < 8; j++) {
                    float* a4 = acc[ii][j];
                    asm volatile(
                        "mma.sync.aligned.m16n8k16.row.col.f32.f16.f16.f32 "
                        "{%0,%1,%2,%3},{%4,%5,%6,%7},{%8,%9},{%0,%1,%2,%3};"
                        : "+f"(a4[0]), "+f"(a4[1]), "+f"(a4[2]), "+f"(a4[3])
                        : "r"(af[ii][0]), "r"(af[ii][1]), "r"(af[ii][2]), "r"(af[ii][3]),
                          "r"(bf[j][0]), "r"(bf[j][1]));
                }
            }
        }
    }
    asm volatile("cp.async.wait_group 0;");

    // Epilogue: +bias, optional sigmoid, write z or c as fp16
    int r  = lane >> 2;
    int cq = (lane & 3) * 2;
    const float* bias = isGate ? bg : bc;
    __half* outp = isGate ? g_zh : g_ch;
    #pragma unroll
    for (int ii = 0; ii < 4; ii++) {
        #pragma unroll
        for (int j = 0; j < 8; j++) {
            float* a4 = acc[ii][j];
            int m0 = bm * BM + wm + ii * 16 + r;
            int n0 = nbase + wn + j * 8 + cq;
            float b0 = bias[n0], b1 = bias[n0 + 1];
            float v0 = a4[0] + b0;
            float v1 = a4[1] + b1;
            float v2 = a4[2] + b0;
            float v3 = a4[3] + b1;
            if (isGate) {
                v0 = 1.f / (1.f + __expf(-v0));
                v1 = 1.f / (1.f + __expf(-v1));
                v2 = 1.f / (1.f + __expf(-v2));
                v3 = 1.f / (1.f + __expf(-v3));
            }
            *(__half2*)(outp + (size_t)m0 * HH + n0)       = __floats2half2_rn(v0, v1);
            *(__half2*)(outp + (size_t)(m0 + 8) * HH + n0) = __floats2half2_rn(v2, v3);
        }
    }
}

// ---------------------------------------------------------------------------
// Scan phase A: per-(b, chunk, hid) aggregates. 2 hids/thread via half2,
// CHUNK=32 -> 1024 CTAs. Interleaved float4 (P,S) store; deeper unroll for MLP.
// ---------------------------------------------------------------------------
__global__ __launch_bounds__(256) void scanA_kernel() {
    int g2  = blockIdx.x * blockDim.x + threadIdx.x;   // over BB*NCHUNK*HH/2
    int hp  = g2 % (HH / 2);
    int ck  = (g2 / (HH / 2)) % NCHUNK;
    int b   = g2 / ((HH / 2) * NCHUNK);
    size_t base = ((size_t)(b * TT + ck * CHUNK)) * HH + 2 * hp;
    float2 P = make_float2(1.f, 1.f), S = make_float2(0.f, 0.f);
    #pragma unroll 16
    for (int t = 0; t < CHUNK; t++) {
        size_t idx = base + (size_t)t * HH;
        float2 z = __half22float2(*(const __half2*)(g_zh + idx));
        float2 c = __half22float2(*(const __half2*)(g_ch + idx));
        float ax = 1.f - z.x, ay = 1.f - z.y;
        S.x = ax * S.x + z.x * c.x;  P.x *= ax;
        S.y = ay * S.y + z.y * c.y;  P.y *= ay;
    }
    size_t o = ((size_t)(b * NCHUNK + ck)) * (HH / 2) + hp;
    g_PS[o] = make_float4(P.x, P.y, S.x, S.y);
}

// ---------------------------------------------------------------------------
// Scan phase B: Kogge-Stone over 128 chunk aggregates per (b, hid-pair).
// One warp per (b,hp); float2 lanes, each lane composes 4 consecutive
// chunks (16B coalesced loads), 5-step shfl scan, emits 4 h_in float2.
// ---------------------------------------------------------------------------
__global__ void scanB_kernel() {
    int gt   = blockIdx.x * blockDim.x + threadIdx.x;
    int lane = gt & 31;
    int wg   = gt >> 5;                 // 0..BB*HH/2-1
    int hp   = wg & (HH / 2 - 1);
    int b    = wg >> 9;                 // HH/2 = 512
    int k0   = 4 * lane;
    size_t i0 = ((size_t)(b * NCHUNK + k0)) * (HH / 2) + hp;
    float4 PS[4];
    #pragma unroll
    for (int q = 0; q < 4; q++)
        PS[q] = g_PS[i0 + (size_t)q * (HH / 2)];
    float2 cP = make_float2(PS[0].x, PS[0].y);
    float2 cS = make_float2(PS[0].z, PS[0].w);
    #pragma unroll
    for (int q = 1; q < 4; q++) {
        cS.x = PS[q].x * cS.x + PS[q].z;  cP.x *= PS[q].x;
        cS.y = PS[q].y * cS.y + PS[q].w;  cP.y *= PS[q].y;
    }
    #pragma unroll
    for (int d = 1; d < 32; d <<= 1) {
        float pPx = __shfl_up_sync(0xFFFFFFFFu, cP.x, d);
        float pPy = __shfl_up_sync(0xFFFFFFFFu, cP.y, d);
        float pSx = __shfl_up_sync(0xFFFFFFFFu, cS.x, d);
        float pSy = __shfl_up_sync(0xFFFFFFFFu, cS.y, d);
        if (lane >= d) {
            cS.x = cP.x * pSx + cS.x;  cP.x = cP.x * pPx;
            cS.y = cP.y * pSy + cS.y;  cP.y = cP.y * pPy;
        }
    }
    float2 h;
    h.x = __shfl_up_sync(0xFFFFFFFFu, cS.x, 1);
    h.y = __shfl_up_sync(0xFFFFFFFFu, cS.y, 1);
    if (lane == 0) { h.x = 0.f; h.y = 0.f; }
    float2* H2 = (float2*)g_hin;
    #pragma unroll
    for (int q = 0; q < 4; q++) {
        size_t idx = i0 + (size_t)q * (HH / 2);
        H2[idx] = h;
        h.x = PS[q].x * h.x + PS[q].z;
        h.y = PS[q].y * h.y + PS[q].w;
    }
}

// ---------------------------------------------------------------------------
// Scan phase C: re-run each chunk with the correct h_in, fuse residual +x.
// 2 hids/thread; CHUNK=32 -> 1024 CTAs.
// ---------------------------------------------------------------------------
__global__ void scanC_kernel(const float* __restrict__ x, float* __restrict__ out) {
    int g2  = blockIdx.x * blockDim.x + threadIdx.x;   // over BB*NCHUNK*HH/2
    int hp  = g2 % (HH / 2);
    int ck  = (g2 / (HH / 2)) % NCHUNK;
    int b   = g2 / ((HH / 2) * NCHUNK);
    size_t base = ((size_t)(b * TT + ck * CHUNK)) * HH + 2 * hp;
    float2 h = ((const float2*)g_hin)[((size_t)(b * NCHUNK + ck)) * (HH / 2) + hp];
    #pragma unroll 8
    for (int t = 0; t < CHUNK; t++) {
        size_t idx = base + (size_t)t * HH;
        float2 z = __half22float2(*(const __half2*)(g_zh + idx));
        float2 c = __half22float2(*(const __half2*)(g_ch + idx));
        h.x = (1.f - z.x) * h.x + z.x * c.x;
        h.y = (1.f - z.y) * h.y + z.y * c.y;
        float2 xv = *(const float2*)(x + idx);
        *(float2*)(out + idx) = make_float2(h.x + xv.x, h.y + xv.y);
    }
}

// ---------------------------------------------------------------------------
extern "C" void kernel_launch(void* const* d_in, const int* in_sizes, int n_in,
                              void* d_out, int out_size) {
    const float* x     = (const float*)d_in[0];
    const float* gamma = (const float*)d_in[1];
    const float* beta  = (const float*)d_in[2];
    const float* Wg    = (const float*)d_in[3];
    const float* bg    = (const float*)d_in[4];
    const float* Wc    = (const float*)d_in[5];
    const float* bc    = (const float*)d_in[6];
    float* out = (float*)d_out;

    halfW_kernel<<<(2 * HH * HH / 4) / 256, 256>>>(Wg, Wc);
    ln_kernel<<<M_TOTAL / 8, 256>>>(x, gamma, beta);

    cudaFuncSetAttribute(gemm_kernel,
                         cudaFuncAttributeMaxDynamicSharedMemorySize, GEMM_SMEM);
    dim3 ggrid(2 * HH / BN, M_TOTAL / BM);   // (16, 128)
    gemm_kernel<<<ggrid, 128, GEMM_SMEM>>>(bg, bc);

    scanA_kernel<<<(BB * NCHUNK * HH / 2) / 256, 256>>>();
    scanB_kernel<<<(BB * (HH / 2) * 32) / 256, 256>>>();
    scanC_kernel<<<(BB * NCHUNK * HH / 2) / 256, 256>>>(x, out);
}

// round 15
// speedup vs baseline: 1.1363x; 1.0061x over previous
#include <cuda_runtime.h>
#include <cuda_fp16.h>
#include <cstdint>
#include <math.h>

// Problem dims (fixed by reference setup_inputs)
#define BB 4
#define TT 4096
#define HH 1024
#define M_TOTAL (BB*TT)      // 16384
#define NCHUNK 128
#define CHUNK (TT/NCHUNK)    // 32

// Scratch (allocation-free rule: __device__ globals)
__device__ __half g_normh[(size_t)M_TOTAL*HH];   // fp16 LN output (32MB)
__device__ __half g_Wh[(size_t)2*HH*HH];         // fp16 [Wg; Wc] (4MB)
__device__ __half g_zh[(size_t)M_TOTAL*HH];      // fp16 gate (32MB)
__device__ __half g_ch[(size_t)M_TOTAL*HH];      // fp16 candidate (32MB)
__device__ float4 g_PS[(size_t)BB*NCHUNK*HH/2];  // interleaved (Px,Py,Sx,Sy) per hp (4MB)
__device__ float g_hin[(size_t)BB*NCHUNK*HH];

__device__ __forceinline__ uint32_t smem_u32(const void* p) {
    uint32_t a;
    asm("{ .reg .u64 t; cvta.to.shared.u64 t, %1; cvt.u32.u64 %0, t; }" : "=r"(a) : "l"(p));
    return a;
}
__device__ __forceinline__ void cp16(uint32_t dst, const void* src) {
    asm volatile("cp.async.cg.shared.global [%0], [%1], 16;" :: "r"(dst), "l"(src));
}

// ---------------------------------------------------------------------------
// Kernel 1: fused LayerNorm + weight conversion (role-split grid).
// Blocks [0, M_TOTAL/8): LN warp-per-row -> fp16 normed.
// Blocks [M_TOTAL/8, +2048): convert Wg/Wc float4-chunks -> g_Wh.
// ---------------------------------------------------------------------------
#define LN_BLOCKS (M_TOTAL / 8)          // 2048
#define HW_BLOCKS ((2 * HH * HH / 4) / 256)  // 2048

__global__ __launch_bounds__(256) void ln_halfw_kernel(
    const float* __restrict__ x,
    const float* __restrict__ gamma,
    const float* __restrict__ beta,
    const float* __restrict__ Wg,
    const float* __restrict__ Wc) {
    if (blockIdx.x >= LN_BLOCKS) {
        // ---- weight-conversion role ----
        int i = (blockIdx.x - LN_BLOCKS) * blockDim.x + threadIdx.x;
        int half_n = HH * HH / 4;
        const float4* src = (i < half_n) ? (const float4*)Wg : (const float4*)Wc;
        float4 v = src[(i < half_n) ? i : (i - half_n)];
        __half2 h0 = __floats2half2_rn(v.x, v.y);
        __half2 h1 = __floats2half2_rn(v.z, v.w);
        ((uint2*)g_Wh)[i] = make_uint2(*(uint32_t*)&h0, *(uint32_t*)&h1);
        return;
    }
    // ---- LayerNorm role: warp-per-row, pure shfl reduction ----
    int warp = threadIdx.x >> 5, lane = threadIdx.x & 31;
    int row = blockIdx.x * 8 + warp;
    const float4* xr = (const float4*)(x + (size_t)row * HH);

    float4 v[8];
    float s = 0.f, s2 = 0.f;
    #pragma unroll
    for (int q = 0; q < 8; q++) {
        v[q] = xr[lane + 32 * q];
        s  += v[q].x + v[q].y + v[q].z + v[q].w;
        s2 += v[q].x*v[q].x + v[q].y*v[q].y + v[q].z*v[q].z + v[q].w*v[q].w;
    }
    #pragma unroll
    for (int o = 16; o > 0; o >>= 1) {
        s  += __shfl_xor_sync(0xFFFFFFFFu, s,  o);
        s2 += __shfl_xor_sync(0xFFFFFFFFu, s2, o);
    }
    float mu  = s * (1.f / HH);
    float var = s2 * (1.f / HH) - mu * mu;
    float rs  = rsqrtf(var + 1e-5f);

    uint2* orow = (uint2*)g_normh + (size_t)row * (HH / 4);
    #pragma unroll
    for (int q = 0; q < 8; q++) {
        int f = lane + 32 * q;
        float4 g  = ((const float4*)gamma)[f];
        float4 bt = ((const float4*)beta)[f];
        __half2 h0 = __floats2half2_rn((v[q].x - mu) * rs * g.x + bt.x,
                                       (v[q].y - mu) * rs * g.y + bt.y);
        __half2 h1 = __floats2half2_rn((v[q].z - mu) * rs * g.z + bt.z,
                                       (v[q].w - mu) * rs * g.w + bt.w);
        orow[f] = make_uint2(*(uint32_t*)&h0, *(uint32_t*)&h1);
    }
}

// ---------------------------------------------------------------------------
// Kernel 2: fp16 mma.sync (m16n8k16) GEMM, cp.async 4-stage pipeline,
// ldmatrix fragment loads. Block tile 128x128, BK=32, 4 warps (128 thr),
// warp tile 64x64 (2x2 warp grid). 2 CTAs/SM. At the mma.sync HMMA ceiling.
// Logical N = 2048: bn<8 -> Wg+sigmoid -> g_zh, bn>=8 -> g_ch.
// ---------------------------------------------------------------------------
#define BM 128
#define BN 128
#define BK 32                            // halves per K-tile
#define STAGES 4
#define SSTR_H 40                        // halves per smem row (80B: ldmatrix conflict-free)
#define A_STAGE_H (BM*SSTR_H)            // 5120 halves
#define B_STAGE_H (BN*SSTR_H)
#define GEMM_SMEM (STAGES*(A_STAGE_H+B_STAGE_H)*2)   // 81920 B

__global__ __launch_bounds__(128, 2) void gemm_kernel(
    const float* __restrict__ bg, const float* __restrict__ bc)
{
    extern __shared__ __half smh[];
    uint32_t sA_u = smem_u32(smh);
    uint32_t sB_u = sA_u + STAGES * A_STAGE_H * 2;

    int tid = threadIdx.x;               // 128
    int warp = tid >> 5, lane = tid & 31;
    int bn = blockIdx.x;                 // 0..15 (fast -> wave shares A in L2)
    int bm = blockIdx.y;                 // 0..127
    int wm = (warp & 1) * 64;            // 2 M-warps
    int wn = (warp >> 1) * 64;           // 2 N-warps

    bool isGate = (bn < 8);
    size_t woff = isGate ? 0 : (size_t)HH * HH;
    int nbase = (bn & 7) * BN;
    size_t arow = (size_t)bm * BM;

    const __half* Asrc0 = g_normh + arow * HH;
    const __half* Bsrc0 = g_Wh + woff + (size_t)nbase * HH;

    float acc[4][8][4];                  // 4 m16 x 8 n8 x 4 regs
    #pragma unroll
    for (int i = 0; i < 4; i++)
        #pragma unroll
        for (int j = 0; j < 8; j++)
            #pragma unroll
            for (int q = 0; q < 4; q++) acc[i][j][q] = 0.f;

    // loads: per stage A 512 + B 512 16B-chunks, 128 thr -> 4+4 each
    int lr[4], lc[4];
    #pragma unroll
    for (int q = 0; q < 4; q++) {
        int f = tid + q * 128;
        lr[q] = f >> 2;                  // row 0..127
        lc[q] = (f & 3) * 8;             // half offset in row (16B chunks)
    }

    #define LOAD_STAGE(s, k0) do { \
        uint32_t abase = sA_u + (uint32_t)(s) * A_STAGE_H * 2; \
        uint32_t bbase = sB_u + (uint32_t)(s) * B_STAGE_H * 2; \
        _Pragma("unroll") \
        for (int q = 0; q < 4; q++) { \
            cp16(abase + (uint32_t)(lr[q] * SSTR_H + lc[q]) * 2, \
                 Asrc0 + (size_t)lr[q] * HH + (k0) + lc[q]); \
            cp16(bbase + (uint32_t)(lr[q] * SSTR_H + lc[q]) * 2, \
                 Bsrc0 + (size_t)lr[q] * HH + (k0) + lc[q]); \
        } \
    } while (0)

    LOAD_STAGE(0, 0);
    asm volatile("cp.async.commit_group;");
    LOAD_STAGE(1, BK);
    asm volatile("cp.async.commit_group;");
    LOAD_STAGE(2, 2 * BK);
    asm volatile("cp.async.commit_group;");

    // per-lane ldmatrix address components (bytes)
    uint32_t a_row = (uint32_t)(lane & 15);          // row within m16
    uint32_t a_kb  = ((lane >> 4) & 1) * 16;         // +8 halves
    uint32_t b_row = (uint32_t)((lane & 7) + ((lane >> 4) & 1) * 8);  // row within n16
    uint32_t b_kb  = ((lane >> 3) & 1) * 16;

    const int NK = HH / BK;              // 32
    for (int i = 0; i < NK; i++) {
        int s = i & (STAGES - 1);
        asm volatile("cp.async.wait_group 2;");
        __syncthreads();
        if (i + 3 < NK) {
            int s2 = (i + 3) & (STAGES - 1);
            LOAD_STAGE(s2, (i + 3) * BK);
        }
        asm volatile("cp.async.commit_group;");

        uint32_t abase = sA_u + (uint32_t)s * A_STAGE_H * 2;
        uint32_t bbase = sB_u + (uint32_t)s * B_STAGE_H * 2;

        #pragma unroll
        for (int ks = 0; ks < 2; ks++) {     // two k16 steps per K-tile
            unsigned af[4][4];
            #pragma unroll
            for (int ii = 0; ii < 4; ii++) {
                uint32_t addr = abase + (wm + ii * 16 + a_row) * (SSTR_H * 2)
                                + ks * 32 + a_kb;
                asm volatile(
                    "ldmatrix.sync.aligned.m8n8.x4.shared.b16 {%0,%1,%2,%3}, [%4];"
                    : "=r"(af[ii][0]), "=r"(af[ii][1]), "=r"(af[ii][2]), "=r"(af[ii][3])
                    : "r"(addr));
            }
            unsigned bf[8][2];
            #pragma unroll
            for (int j2 = 0; j2 < 4; j2++) {  // each x4 covers two n8 subtiles
                uint32_t addr = bbase + (wn + j2 * 16 + b_row) * (SSTR_H * 2)
                                + ks * 32 + b_kb;
                asm volatile(
                    "ldmatrix.sync.aligned.m8n8.x4.shared.b16 {%0,%1,%2,%3}, [%4];"
                    : "=r"(bf[j2*2][0]), "=r"(bf[j2*2][1]),
                      "=r"(bf[j2*2+1][0]), "=r"(bf[j2*2+1][1])
                    : "r"(addr));
            }
            #pragma unroll
            for (int ii = 0; ii < 4; ii++) {
                #pragma unroll
                for (int j = 0; j < 8; j++) {
                    float* a4 = acc[ii][j];
                    asm volatile(
                        "mma.sync.aligned.m16n8k16.row.col.f32.f16.f16.f32 "
                        "{%0,%1,%2,%3},{%4,%5,%6,%7},{%8,%9},{%0,%1,%2,%3};"
                        : "+f"(a4[0]), "+f"(a4[1]), "+f"(a4[2]), "+f"(a4[3])
                        : "r"(af[ii][0]), "r"(af[ii][1]), "r"(af[ii][2]), "r"(af[ii][3]),
                          "r"(bf[j][0]), "r"(bf[j][1]));
                }
            }
        }
    }
    asm volatile("cp.async.wait_group 0;");

    // Epilogue: +bias, optional sigmoid, write z or c as fp16
    int r  = lane >> 2;
    int cq = (lane & 3) * 2;
    const float* bias = isGate ? bg : bc;
    __half* outp = isGate ? g_zh : g_ch;
    #pragma unroll
    for (int ii = 0; ii < 4; ii++) {
        #pragma unroll
        for (int j = 0; j < 8; j++) {
            float* a4 = acc[ii][j];
            int m0 = bm * BM + wm + ii * 16 + r;
            int n0 = nbase + wn + j * 8 + cq;
            float b0 = bias[n0], b1 = bias[n0 + 1];
            float v0 = a4[0] + b0;
            float v1 = a4[1] + b1;
            float v2 = a4[2] + b0;
            float v3 = a4[3] + b1;
            if (isGate) {
                v0 = 1.f / (1.f + __expf(-v0));
                v1 = 1.f / (1.f + __expf(-v1));
                v2 = 1.f / (1.f + __expf(-v2));
                v3 = 1.f / (1.f + __expf(-v3));
            }
            *(__half2*)(outp + (size_t)m0 * HH + n0)       = __floats2half2_rn(v0, v1);
            *(__half2*)(outp + (size_t)(m0 + 8) * HH + n0) = __floats2half2_rn(v2, v3);
        }
    }
}

// ---------------------------------------------------------------------------
// Scan phase A: per-(b, chunk, hid) aggregates. 2 hids/thread via half2.
// Dependency-chain split: two independent 16-step scans (t in [0,16) and
// [16,32)) interleaved for 2x FFMA ILP, composed at the end:
//   P = P1*P2,  S = P2*S1 + S2.
// ---------------------------------------------------------------------------
__global__ __launch_bounds__(256) void scanA_kernel() {
    int g2  = blockIdx.x * blockDim.x + threadIdx.x;   // over BB*NCHUNK*HH/2
    int hp  = g2 % (HH / 2);
    int ck  = (g2 / (HH / 2)) % NCHUNK;
    int b   = g2 / ((HH / 2) * NCHUNK);
    size_t base = ((size_t)(b * TT + ck * CHUNK)) * HH + 2 * hp;
    float2 P1 = make_float2(1.f, 1.f), S1 = make_float2(0.f, 0.f);
    float2 P2 = make_float2(1.f, 1.f), S2 = make_float2(0.f, 0.f);
    #pragma unroll
    for (int t = 0; t < CHUNK / 2; t++) {
        size_t i1 = base + (size_t)t * HH;
        size_t i2 = base + (size_t)(t + CHUNK / 2) * HH;
        float2 za = __half22float2(*(const __half2*)(g_zh + i1));
        float2 ca = __half22float2(*(const __half2*)(g_ch + i1));
        float2 zb = __half22float2(*(const __half2*)(g_zh + i2));
        float2 cb = __half22float2(*(const __half2*)(g_ch + i2));
        float a0 = 1.f - za.x, a1 = 1.f - za.y;
        float b0 = 1.f - zb.x, b1 = 1.f - zb.y;
        S1.x = a0 * S1.x + za.x * ca.x;  P1.x *= a0;
        S1.y = a1 * S1.y + za.y * ca.y;  P1.y *= a1;
        S2.x = b0 * S2.x + zb.x * cb.x;  P2.x *= b0;
        S2.y = b1 * S2.y + zb.y * cb.y;  P2.y *= b1;
    }
    float4 PS;
    PS.x = P1.x * P2.x;
    PS.y = P1.y * P2.y;
    PS.z = P2.x * S1.x + S2.x;
    PS.w = P2.y * S1.y + S2.y;
    size_t o = ((size_t)(b * NCHUNK + ck)) * (HH / 2) + hp;
    g_PS[o] = PS;
}

// ---------------------------------------------------------------------------
// Scan phase B: Kogge-Stone over 128 chunk aggregates per (b, hid-pair).
// One warp per (b,hp); float2 lanes, each lane composes 4 consecutive
// chunks (16B coalesced loads), 5-step shfl scan, emits 4 h_in float2.
// ---------------------------------------------------------------------------
__global__ void scanB_kernel() {
    int gt   = blockIdx.x * blockDim.x + threadIdx.x;
    int lane = gt & 31;
    int wg   = gt >> 5;                 // 0..BB*HH/2-1
    int hp   = wg & (HH / 2 - 1);
    int b    = wg >> 9;                 // HH/2 = 512
    int k0   = 4 * lane;
    size_t i0 = ((size_t)(b * NCHUNK + k0)) * (HH / 2) + hp;
    float4 PS[4];
    #pragma unroll
    for (int q = 0; q < 4; q++)
        PS[q] = g_PS[i0 + (size_t)q * (HH / 2)];
    float2 cP = make_float2(PS[0].x, PS[0].y);
    float2 cS = make_float2(PS[0].z, PS[0].w);
    #pragma unroll
    for (int q = 1; q < 4; q++) {
        cS.x = PS[q].x * cS.x + PS[q].z;  cP.x *= PS[q].x;
        cS.y = PS[q].y * cS.y + PS[q].w;  cP.y *= PS[q].y;
    }
    #pragma unroll
    for (int d = 1; d < 32; d <<= 1) {
        float pPx = __shfl_up_sync(0xFFFFFFFFu, cP.x, d);
        float pPy = __shfl_up_sync(0xFFFFFFFFu, cP.y, d);
        float pSx = __shfl_up_sync(0xFFFFFFFFu, cS.x, d);
        float pSy = __shfl_up_sync(0xFFFFFFFFu, cS.y, d);
        if (lane >= d) {
            cS.x = cP.x * pSx + cS.x;  cP.x = cP.x * pPx;
            cS.y = cP.y * pSy + cS.y;  cP.y = cP.y * pPy;
        }
    }
    float2 h;
    h.x = __shfl_up_sync(0xFFFFFFFFu, cS.x, 1);
    h.y = __shfl_up_sync(0xFFFFFFFFu, cS.y, 1);
    if (lane == 0) { h.x = 0.f; h.y = 0.f; }
    float2* H2 = (float2*)g_hin;
    #pragma unroll
    for (int q = 0; q < 4; q++) {
        size_t idx = i0 + (size_t)q * (HH / 2);
        H2[idx] = h;
        h.x = PS[q].x * h.x + PS[q].z;
        h.y = PS[q].y * h.y + PS[q].w;
    }
}

// ---------------------------------------------------------------------------
// Scan phase C: re-run each chunk with the correct h_in, fuse residual +x.
// 2 hids/thread; CHUNK=32 -> 1024 CTAs.
// ---------------------------------------------------------------------------
__global__ void scanC_kernel(const float* __restrict__ x, float* __restrict__ out) {
    int g2  = blockIdx.x * blockDim.x + threadIdx.x;   // over BB*NCHUNK*HH/2
    int hp  = g2 % (HH / 2);
    int ck  = (g2 / (HH / 2)) % NCHUNK;
    int b   = g2 / ((HH / 2) * NCHUNK);
    size_t base = ((size_t)(b * TT + ck * CHUNK)) * HH + 2 * hp;
    float2 h = ((const float2*)g_hin)[((size_t)(b * NCHUNK + ck)) * (HH / 2) + hp];
    #pragma unroll 8
    for (int t = 0; t < CHUNK; t++) {
        size_t idx = base + (size_t)t * HH;
        float2 z = __half22float2(*(const __half2*)(g_zh + idx));
        float2 c = __half22float2(*(const __half2*)(g_ch + idx));
        h.x = (1.f - z.x) * h.x + z.x * c.x;
        h.y = (1.f - z.y) * h.y + z.y * c.y;
        float2 xv = *(const float2*)(x + idx);
        *(float2*)(out + idx) = make_float2(h.x + xv.x, h.y + xv.y);
    }
}

// ---------------------------------------------------------------------------
extern "C" void kernel_launch(void* const* d_in, const int* in_sizes, int n_in,
                              void* d_out, int out_size) {
    const float* x     = (const float*)d_in[0];
    const float* gamma = (const float*)d_in[1];
    const float* beta  = (const float*)d_in[2];
    const float* Wg    = (const float*)d_in[3];
    const float* bg    = (const float*)d_in[4];
    const float* Wc    = (const float*)d_in[5];
    const float* bc    = (const float*)d_in[6];
    float* out = (float*)d_out;

    ln_halfw_kernel<<<LN_BLOCKS + HW_BLOCKS, 256>>>(x, gamma, beta, Wg, Wc);

    cudaFuncSetAttribute(gemm_kernel,
                         cudaFuncAttributeMaxDynamicSharedMemorySize, GEMM_SMEM);
    dim3 ggrid(2 * HH / BN, M_TOTAL / BM);   // (16, 128)
    gemm_kernel<<<ggrid, 128, GEMM_SMEM>>>(bg, bc);

    scanA_kernel<<<(BB * NCHUNK * HH / 2) / 256, 256>>>();
    scanB_kernel<<<(BB * (HH / 2) * 32) / 256, 256>>>();
    scanC_kernel<<<(BB * NCHUNK * HH / 2) / 256, 256>>>(x, out);
}

// round 16
// speedup vs baseline: 1.1427x; 1.0056x over previous
#include <cuda_runtime.h>
#include <cuda_fp16.h>
#include <cstdint>
#include <math.h>

// Problem dims (fixed by reference setup_inputs)
#define BB 4
#define TT 4096
#define HH 1024
#define M_TOTAL (BB*TT)      // 16384
#define NCHUNK 128
#define CHUNK (TT/NCHUNK)    // 32

// Scratch (allocation-free rule: __device__ globals)
__device__ __half g_normh[(size_t)M_TOTAL*HH];   // fp16 LN output (32MB)
__device__ __half g_Wh[(size_t)2*HH*HH];         // fp16 [Wg; Wc] (4MB)
__device__ __half g_zh[(size_t)M_TOTAL*HH];      // fp16 gate (32MB)
__device__ __half g_ch[(size_t)M_TOTAL*HH];      // fp16 candidate (32MB)
// Chunk-scan state, TRANSPOSED layout [b][hp][ck] so scanB is coalesced:
__device__ float4 g_PS[(size_t)BB*(HH/2)*NCHUNK];   // (Px,Py,Sx,Sy) (4MB)
__device__ float2 g_hin2[(size_t)BB*(HH/2)*NCHUNK]; // h_in pairs (4MB)

__device__ __forceinline__ uint32_t smem_u32(const void* p) {
    uint32_t a;
    asm("{ .reg .u64 t; cvta.to.shared.u64 t, %1; cvt.u32.u64 %0, t; }" : "=r"(a) : "l"(p));
    return a;
}
__device__ __forceinline__ void cp16(uint32_t dst, const void* src) {
    asm volatile("cp.async.cg.shared.global [%0], [%1], 16;" :: "r"(dst), "l"(src));
}

// ---------------------------------------------------------------------------
// Kernel 1: fused LayerNorm + weight conversion (role-split grid).
// Blocks [0, M_TOTAL/8): LN warp-per-row -> fp16 normed.
// Blocks [M_TOTAL/8, +2048): convert Wg/Wc float4-chunks -> g_Wh.
// ---------------------------------------------------------------------------
#define LN_BLOCKS (M_TOTAL / 8)          // 2048
#define HW_BLOCKS ((2 * HH * HH / 4) / 256)  // 2048

__global__ __launch_bounds__(256) void ln_halfw_kernel(
    const float* __restrict__ x,
    const float* __restrict__ gamma,
    const float* __restrict__ beta,
    const float* __restrict__ Wg,
    const float* __restrict__ Wc) {
    if (blockIdx.x >= LN_BLOCKS) {
        // ---- weight-conversion role ----
        int i = (blockIdx.x - LN_BLOCKS) * blockDim.x + threadIdx.x;
        int half_n = HH * HH / 4;
        const float4* src = (i < half_n) ? (const float4*)Wg : (const float4*)Wc;
        float4 v = src[(i < half_n) ? i : (i - half_n)];
        __half2 h0 = __floats2half2_rn(v.x, v.y);
        __half2 h1 = __floats2half2_rn(v.z, v.w);
        ((uint2*)g_Wh)[i] = make_uint2(*(uint32_t*)&h0, *(uint32_t*)&h1);
        return;
    }
    // ---- LayerNorm role: warp-per-row, pure shfl reduction ----
    int warp = threadIdx.x >> 5, lane = threadIdx.x & 31;
    int row = blockIdx.x * 8 + warp;
    const float4* xr = (const float4*)(x + (size_t)row * HH);

    float4 v[8];
    float s = 0.f, s2 = 0.f;
    #pragma unroll
    for (int q = 0; q < 8; q++) {
        v[q] = xr[lane + 32 * q];
        s  += v[q].x + v[q].y + v[q].z + v[q].w;
        s2 += v[q].x*v[q].x + v[q].y*v[q].y + v[q].z*v[q].z + v[q].w*v[q].w;
    }
    #pragma unroll
    for (int o = 16; o > 0; o >>= 1) {
        s  += __shfl_xor_sync(0xFFFFFFFFu, s,  o);
        s2 += __shfl_xor_sync(0xFFFFFFFFu, s2, o);
    }
    float mu  = s * (1.f / HH);
    float var = s2 * (1.f / HH) - mu * mu;
    float rs  = rsqrtf(var + 1e-5f);

    uint2* orow = (uint2*)g_normh + (size_t)row * (HH / 4);
    #pragma unroll
    for (int q = 0; q < 8; q++) {
        int f = lane + 32 * q;
        float4 g  = ((const float4*)gamma)[f];
        float4 bt = ((const float4*)beta)[f];
        __half2 h0 = __floats2half2_rn((v[q].x - mu) * rs * g.x + bt.x,
                                       (v[q].y - mu) * rs * g.y + bt.y);
        __half2 h1 = __floats2half2_rn((v[q].z - mu) * rs * g.z + bt.z,
                                       (v[q].w - mu) * rs * g.w + bt.w);
        orow[f] = make_uint2(*(uint32_t*)&h0, *(uint32_t*)&h1);
    }
}

// ---------------------------------------------------------------------------
// Kernel 2: fp16 mma.sync (m16n8k16) GEMM, cp.async 4-stage pipeline,
// ldmatrix fragment loads. Block tile 128x128, BK=32, 4 warps (128 thr),
// warp tile 64x64 (2x2 warp grid). 2 CTAs/SM. At the mma.sync HMMA ceiling.
// Logical N = 2048: bn<8 -> Wg+sigmoid -> g_zh, bn>=8 -> g_ch.
// ---------------------------------------------------------------------------
#define BM 128
#define BN 128
#define BK 32                            // halves per K-tile
#define STAGES 4
#define SSTR_H 40                        // halves per smem row (80B: ldmatrix conflict-free)
#define A_STAGE_H (BM*SSTR_H)            // 5120 halves
#define B_STAGE_H (BN*SSTR_H)
#define GEMM_SMEM (STAGES*(A_STAGE_H+B_STAGE_H)*2)   // 81920 B

__global__ __launch_bounds__(128, 2) void gemm_kernel(
    const float* __restrict__ bg, const float* __restrict__ bc)
{
    extern __shared__ __half smh[];
    uint32_t sA_u = smem_u32(smh);
    uint32_t sB_u = sA_u + STAGES * A_STAGE_H * 2;

    int tid = threadIdx.x;               // 128
    int warp = tid >> 5, lane = tid & 31;
    int bn = blockIdx.x;                 // 0..15 (fast -> wave shares A in L2)
    int bm = blockIdx.y;                 // 0..127
    int wm = (warp & 1) * 64;            // 2 M-warps
    int wn = (warp >> 1) * 64;           // 2 N-warps

    bool isGate = (bn < 8);
    size_t woff = isGate ? 0 : (size_t)HH * HH;
    int nbase = (bn & 7) * BN;
    size_t arow = (size_t)bm * BM;

    const __half* Asrc0 = g_normh + arow * HH;
    const __half* Bsrc0 = g_Wh + woff + (size_t)nbase * HH;

    float acc[4][8][4];                  // 4 m16 x 8 n8 x 4 regs
    #pragma unroll
    for (int i = 0; i < 4; i++)
        #pragma unroll
        for (int j = 0; j < 8; j++)
            #pragma unroll
            for (int q = 0; q < 4; q++) acc[i][j][q] = 0.f;

    // loads: per stage A 512 + B 512 16B-chunks, 128 thr -> 4+4 each
    int lr[4], lc[4];
    #pragma unroll
    for (int q = 0; q < 4; q++) {
        int f = tid + q * 128;
        lr[q] = f >> 2;                  // row 0..127
        lc[q] = (f & 3) * 8;             // half offset in row (16B chunks)
    }

    #define LOAD_STAGE(s, k0) do { \
        uint32_t abase = sA_u + (uint32_t)(s) * A_STAGE_H * 2; \
        uint32_t bbase = sB_u + (uint32_t)(s) * B_STAGE_H * 2; \
        _Pragma("unroll") \
        for (int q = 0; q < 4; q++) { \
            cp16(abase + (uint32_t)(lr[q] * SSTR_H + lc[q]) * 2, \
                 Asrc0 + (size_t)lr[q] * HH + (k0) + lc[q]); \
            cp16(bbase + (uint32_t)(lr[q] * SSTR_H + lc[q]) * 2, \
                 Bsrc0 + (size_t)lr[q] * HH + (k0) + lc[q]); \
        } \
    } while (0)

    LOAD_STAGE(0, 0);
    asm volatile("cp.async.commit_group;");
    LOAD_STAGE(1, BK);
    asm volatile("cp.async.commit_group;");
    LOAD_STAGE(2, 2 * BK);
    asm volatile("cp.async.commit_group;");

    // per-lane ldmatrix address components (bytes)
    uint32_t a_row = (uint32_t)(lane & 15);          // row within m16
    uint32_t a_kb  = ((lane >> 4) & 1) * 16;         // +8 halves
    uint32_t b_row = (uint32_t)((lane & 7) + ((lane >> 4) & 1) * 8);  // row within n16
    uint32_t b_kb  = ((lane >> 3) & 1) * 16;

    const int NK = HH / BK;              // 32
    for (int i = 0; i < NK; i++) {
        int s = i & (STAGES - 1);
        asm volatile("cp.async.wait_group 2;");
        __syncthreads();
        if (i + 3 < NK) {
            int s2 = (i + 3) & (STAGES - 1);
            LOAD_STAGE(s2, (i + 3) * BK);
        }
        asm volatile("cp.async.commit_group;");

        uint32_t abase = sA_u + (uint32_t)s * A_STAGE_H * 2;
        uint32_t bbase = sB_u + (uint32_t)s * B_STAGE_H * 2;

        #pragma unroll
        for (int ks = 0; ks < 2; ks++) {     // two k16 steps per K-tile
            unsigned af[4][4];
            #pragma unroll
            for (int ii = 0; ii < 4; ii++) {
                uint32_t addr = abase + (wm + ii * 16 + a_row) * (SSTR_H * 2)
                                + ks * 32 + a_kb;
                asm volatile(
                    "ldmatrix.sync.aligned.m8n8.x4.shared.b16 {%0,%1,%2,%3}, [%4];"
                    : "=r"(af[ii][0]), "=r"(af[ii][1]), "=r"(af[ii][2]), "=r"(af[ii][3])
                    : "r"(addr));
            }
            unsigned bf[8][2];
            #pragma unroll
            for (int j2 = 0; j2 < 4; j2++) {  // each x4 covers two n8 subtiles
                uint32_t addr = bbase + (wn + j2 * 16 + b_row) * (SSTR_H * 2)
                                + ks * 32 + b_kb;
                asm volatile(
                    "ldmatrix.sync.aligned.m8n8.x4.shared.b16 {%0,%1,%2,%3}, [%4];"
                    : "=r"(bf[j2*2][0]), "=r"(bf[j2*2][1]),
                      "=r"(bf[j2*2+1][0]), "=r"(bf[j2*2+1][1])
                    : "r"(addr));
            }
            #pragma unroll
            for (int ii = 0; ii < 4; ii++) {
                #pragma unroll
                for (int j = 0; j < 8; j++) {
                    float* a4 = acc[ii][j];
                    asm volatile(
                        "mma.sync.aligned.m16n8k16.row.col.f32.f16.f16.f32 "
                        "{%0,%1,%2,%3},{%4,%5,%6,%7},{%8,%9},{%0,%1,%2,%3};"
                        : "+f"(a4[0]), "+f"(a4[1]), "+f"(a4[2]), "+f"(a4[3])
                        : "r"(af[ii][0]), "r"(af[ii][1]), "r"(af[ii][2]), "r"(af[ii][3]),
                          "r"(bf[j][0]), "r"(bf[j][1]));
                }
            }
        }
    }
    asm volatile("cp.async.wait_group 0;");

    // Epilogue: +bias, optional sigmoid, write z or c as fp16
    int r  = lane >> 2;
    int cq = (lane & 3) * 2;
    const float* bias = isGate ? bg : bc;
    __half* outp = isGate ? g_zh : g_ch;
    #pragma unroll
    for (int ii = 0; ii < 4; ii++) {
        #pragma unroll
        for (int j = 0; j < 8; j++) {
            float* a4 = acc[ii][j];
            int m0 = bm * BM + wm + ii * 16 + r;
            int n0 = nbase + wn + j * 8 + cq;
            float b0 = bias[n0], b1 = bias[n0 + 1];
            float v0 = a4[0] + b0;
            float v1 = a4[1] + b1;
            float v2 = a4[2] + b0;
            float v3 = a4[3] + b1;
            if (isGate) {
                v0 = 1.f / (1.f + __expf(-v0));
                v1 = 1.f / (1.f + __expf(-v1));
                v2 = 1.f / (1.f + __expf(-v2));
                v3 = 1.f / (1.f + __expf(-v3));
            }
            *(__half2*)(outp + (size_t)m0 * HH + n0)       = __floats2half2_rn(v0, v1);
            *(__half2*)(outp + (size_t)(m0 + 8) * HH + n0) = __floats2half2_rn(v2, v3);
        }
    }
}

// ---------------------------------------------------------------------------
// Scan phase A: per-(b, chunk, hid) aggregates. 2 hids/thread via half2.
// Split dependency chain (two independent 16-step scans, composed at end).
// Stores to TRANSPOSED g_PS[b][hp][ck] (scattered 16B store, once/thread).
// ---------------------------------------------------------------------------
__global__ __launch_bounds__(256) void scanA_kernel() {
    int g2  = blockIdx.x * blockDim.x + threadIdx.x;   // over BB*NCHUNK*HH/2
    int hp  = g2 % (HH / 2);
    int ck  = (g2 / (HH / 2)) % NCHUNK;
    int b   = g2 / ((HH / 2) * NCHUNK);
    size_t base = ((size_t)(b * TT + ck * CHUNK)) * HH + 2 * hp;
    float2 P1 = make_float2(1.f, 1.f), S1 = make_float2(0.f, 0.f);
    float2 P2 = make_float2(1.f, 1.f), S2 = make_float2(0.f, 0.f);
    #pragma unroll
    for (int t = 0; t < CHUNK / 2; t++) {
        size_t i1 = base + (size_t)t * HH;
        size_t i2 = base + (size_t)(t + CHUNK / 2) * HH;
        float2 za = __half22float2(*(const __half2*)(g_zh + i1));
        float2 ca = __half22float2(*(const __half2*)(g_ch + i1));
        float2 zb = __half22float2(*(const __half2*)(g_zh + i2));
        float2 cb = __half22float2(*(const __half2*)(g_ch + i2));
        float a0 = 1.f - za.x, a1 = 1.f - za.y;
        float b0 = 1.f - zb.x, b1 = 1.f - zb.y;
        S1.x = a0 * S1.x + za.x * ca.x;  P1.x *= a0;
        S1.y = a1 * S1.y + za.y * ca.y;  P1.y *= a1;
        S2.x = b0 * S2.x + zb.x * cb.x;  P2.x *= b0;
        S2.y = b1 * S2.y + zb.y * cb.y;  P2.y *= b1;
    }
    float4 PS;
    PS.x = P1.x * P2.x;
    PS.y = P1.y * P2.y;
    PS.z = P2.x * S1.x + S2.x;
    PS.w = P2.y * S1.y + S2.y;
    size_t o = ((size_t)(b * (HH / 2) + hp)) * NCHUNK + ck;   // transposed
    g_PS[o] = PS;
}

// ---------------------------------------------------------------------------
// Scan phase B: Kogge-Stone over 128 chunk aggregates per (b, hid-pair).
// One warp per (b,hp). Transposed layout: lane l owns chunks 4l..4l+3 at
// CONSECUTIVE addresses -> fully coalesced 64B/lane loads and stores.
// ---------------------------------------------------------------------------
__global__ void scanB_kernel() {
    int gt   = blockIdx.x * blockDim.x + threadIdx.x;
    int lane = gt & 31;
    int wg   = gt >> 5;                 // 0..BB*HH/2-1  (= b*(HH/2)+hp)
    size_t base = (size_t)wg * NCHUNK + 4 * lane;
    float4 PS[4];
    #pragma unroll
    for (int q = 0; q < 4; q++)
        PS[q] = g_PS[base + q];
    float2 cP = make_float2(PS[0].x, PS[0].y);
    float2 cS = make_float2(PS[0].z, PS[0].w);
    #pragma unroll
    for (int q = 1; q < 4; q++) {
        cS.x = PS[q].x * cS.x + PS[q].z;  cP.x *= PS[q].x;
        cS.y = PS[q].y * cS.y + PS[q].w;  cP.y *= PS[q].y;
    }
    #pragma unroll
    for (int d = 1; d < 32; d <<= 1) {
        float pPx = __shfl_up_sync(0xFFFFFFFFu, cP.x, d);
        float pPy = __shfl_up_sync(0xFFFFFFFFu, cP.y, d);
        float pSx = __shfl_up_sync(0xFFFFFFFFu, cS.x, d);
        float pSy = __shfl_up_sync(0xFFFFFFFFu, cS.y, d);
        if (lane >= d) {
            cS.x = cP.x * pSx + cS.x;  cP.x = cP.x * pPx;
            cS.y = cP.y * pSy + cS.y;  cP.y = cP.y * pPy;
        }
    }
    float2 h;
    h.x = __shfl_up_sync(0xFFFFFFFFu, cS.x, 1);
    h.y = __shfl_up_sync(0xFFFFFFFFu, cS.y, 1);
    if (lane == 0) { h.x = 0.f; h.y = 0.f; }
    #pragma unroll
    for (int q = 0; q < 4; q++) {
        g_hin2[base + q] = h;
        h.x = PS[q].x * h.x + PS[q].z;
        h.y = PS[q].y * h.y + PS[q].w;
    }
}

// ---------------------------------------------------------------------------
// Scan phase C: re-run each chunk with the correct h_in, fuse residual +x.
// 2 hids/thread; h_in read from transposed layout (once per thread).
// ---------------------------------------------------------------------------
__global__ void scanC_kernel(const float* __restrict__ x, float* __restrict__ out) {
    int g2  = blockIdx.x * blockDim.x + threadIdx.x;   // over BB*NCHUNK*HH/2
    int hp  = g2 % (HH / 2);
    int ck  = (g2 / (HH / 2)) % NCHUNK;
    int b   = g2 / ((HH / 2) * NCHUNK);
    size_t base = ((size_t)(b * TT + ck * CHUNK)) * HH + 2 * hp;
    float2 h = g_hin2[((size_t)(b * (HH / 2) + hp)) * NCHUNK + ck];
    #pragma unroll 8
    for (int t = 0; t < CHUNK; t++) {
        size_t idx = base + (size_t)t * HH;
        float2 z = __half22float2(*(const __half2*)(g_zh + idx));
        float2 c = __half22float2(*(const __half2*)(g_ch + idx));
        h.x = (1.f - z.x) * h.x + z.x * c.x;
        h.y = (1.f - z.y) * h.y + z.y * c.y;
        float2 xv = *(const float2*)(x + idx);
        *(float2*)(out + idx) = make_float2(h.x + xv.x, h.y + xv.y);
    }
}

// ---------------------------------------------------------------------------
extern "C" void kernel_launch(void* const* d_in, const int* in_sizes, int n_in,
                              void* d_out, int out_size) {
    const float* x     = (const float*)d_in[0];
    const float* gamma = (const float*)d_in[1];
    const float* beta  = (const float*)d_in[2];
    const float* Wg    = (const float*)d_in[3];
    const float* bg    = (const float*)d_in[4];
    const float* Wc    = (const float*)d_in[5];
    const float* bc    = (const float*)d_in[6];
    float* out = (float*)d_out;

    ln_halfw_kernel<<<LN_BLOCKS + HW_BLOCKS, 256>>>(x, gamma, beta, Wg, Wc);

    cudaFuncSetAttribute(gemm_kernel,
                         cudaFuncAttributeMaxDynamicSharedMemorySize, GEMM_SMEM);
    dim3 ggrid(2 * HH / BN, M_TOTAL / BM);   // (16, 128)
    gemm_kernel<<<ggrid, 128, GEMM_SMEM>>>(bg, bc);

    scanA_kernel<<<(BB * NCHUNK * HH / 2) / 256, 256>>>();
    scanB_kernel<<<(BB * (HH / 2) * 32) / 256, 256>>>();
    scanC_kernel<<<(BB * NCHUNK * HH / 2) / 256, 256>>>(x, out);
}